// round 12
// baseline (speedup 1.0000x reference)
#include <cuda_runtime.h>
#include <cuda_fp16.h>
#include <cstdint>
#include <math.h>

#define N_NODES 50000
#define N_EDGES 800000
#define HID 128
#define EC 100
#define IN_DIM 5
#define N_BLOCKS 6
#define NT 512
#define NTILES 6250
#define NBLK_C 3125   // N_EDGES / 256

// ---------------- scratch (device globals; no runtime allocation) ----------------
__device__ uint32_t g_xh[N_NODES * 64];        // x in half2 (12.8 MB)
__device__ float g_agg[N_NODES * HID];
__device__ uint32_t g_eaf[(size_t)NTILES * 8192];   // compacted eattr frag fp16
__device__ uint32_t g_w1f[6 * 8192];
__device__ uint32_t g_w2f[6 * 8192];
__device__ uint32_t g_l2f[6 * 8192];
__device__ uint32_t g_lf [6 * 8192];
__device__ uint32_t g_l1f[6 * 8192];
// edge compaction
__device__ int g_bcnt[NBLK_C];
__device__ int g_boff[NBLK_C];
__device__ int g_nc;
__device__ int g_srcC[N_EDGES];
__device__ int g_dstC[N_EDGES];
__device__ int g_eidx[N_EDGES];

__device__ __forceinline__ float sspf(float x) {
    float sp = fmaxf(x, 0.0f) + log1pf(expf(-fabsf(x)));
    return sp - 0.69314718055994531f;
}
__device__ __forceinline__ uint32_t h2(float lo, float hi) {
    uint32_t r;
    asm("cvt.rn.f16x2.f32 %0, %1, %2;" : "=r"(r) : "f"(hi), "f"(lo));
    return r;
}

// ---------------- fragment layout constants ----------------
#define KS_STR 132
#define AI_STR 264
#define AWORDS 2112
#define TI_STR 1056
#define TWORDS 8448

#define EDGE_SMEM (TWORDS * 4)
#define NODE_SMEM ((TWORDS + 2 * AWORDS) * 4)
#define PLAIN_SMEM ((2 * AWORDS) * 4)

// ---------------- edge compaction ----------------
__device__ __forceinline__ bool edge_ok(float l) { return (l <= 10.0f && l >= 0.0f); }

__global__ void count_kernel(const float* __restrict__ len) {
    int e = blockIdx.x * 256 + threadIdx.x;
    bool valid = edge_ok(len[e]);
    unsigned m = __ballot_sync(0xffffffffu, valid);
    __shared__ int wc[8];
    if ((threadIdx.x & 31) == 0) wc[threadIdx.x >> 5] = __popc(m);
    __syncthreads();
    if (threadIdx.x == 0) {
        int s = 0;
#pragma unroll
        for (int i = 0; i < 8; i++) s += wc[i];
        g_bcnt[blockIdx.x] = s;
    }
}

__global__ void __launch_bounds__(1024) scan_kernel() {
    __shared__ int smv[1024];
    int tid = threadIdx.x;
    int v[4]; int s = 0;
#pragma unroll
    for (int i = 0; i < 4; i++) {
        int idx = tid * 4 + i;
        v[i] = (idx < NBLK_C) ? g_bcnt[idx] : 0;
        s += v[i];
    }
    smv[tid] = s;
    __syncthreads();
    for (int off = 1; off < 1024; off <<= 1) {
        int x = 0;
        if (tid >= off) x = smv[tid - off];
        __syncthreads();
        if (tid >= off) smv[tid] += x;
        __syncthreads();
    }
    int run = (tid > 0) ? smv[tid - 1] : 0;
#pragma unroll
    for (int i = 0; i < 4; i++) {
        int idx = tid * 4 + i;
        if (idx < NBLK_C) g_boff[idx] = run;
        run += v[i];
    }
    if (tid == 1023) g_nc = smv[1023];
}

__global__ void scatter_kernel(const float* __restrict__ len,
                               const int* __restrict__ src, const int* __restrict__ dst) {
    int e = blockIdx.x * 256 + threadIdx.x;
    bool valid = edge_ok(len[e]);
    unsigned m = __ballot_sync(0xffffffffu, valid);
    int w = threadIdx.x >> 5, lane = threadIdx.x & 31;
    __shared__ int wb[8], wo[8];
    if (lane == 0) wb[w] = __popc(m);
    __syncthreads();
    if (threadIdx.x == 0) {
        int s = 0;
#pragma unroll
        for (int i = 0; i < 8; i++) { wo[i] = s; s += wb[i]; }
    }
    __syncthreads();
    if (valid) {
        int pos = g_boff[blockIdx.x] + wo[w] + __popc(m & ((1u << lane) - 1u));
        g_srcC[pos] = src[e];
        g_dstC[pos] = dst[e];
        g_eidx[pos] = e;
    }
}

__global__ void pad_kernel() {
    int i = blockIdx.x * 256 + threadIdx.x;
    if (i < N_EDGES && i >= g_nc) {
        g_srcC[i] = 0; g_dstC[i] = 0; g_eidx[i] = -1;
    }
}

// ---------------- weight pre-pack ----------------
__global__ void __launch_bounds__(256) pack_w(
    const float* __restrict__ w1, const float* __restrict__ w2,
    const float* __restrict__ l2, const float* __restrict__ l,
    const float* __restrict__ l1,
    uint32_t* __restrict__ o1, uint32_t* __restrict__ o2,
    uint32_t* __restrict__ o3, uint32_t* __restrict__ o4,
    uint32_t* __restrict__ o5)
{
    const float* W; uint32_t* O; int K;
    switch (blockIdx.y) {
        case 0: W = w1; O = o1; K = EC;  break;
        case 1: W = w2; O = o2; K = 128; break;
        case 2: W = l2; O = o3; K = 128; break;
        case 3: W = l;  O = o4; K = 128; break;
        default: W = l1; O = o5; K = 128; break;
    }
    int idx = blockIdx.x * 256 + threadIdx.x;
    if (idx >= 6 * 8192) return;
    int blk = idx >> 13;
    int r = idx & 8191;
    int ch = r >> 11;
    int r2 = r & 2047;
    int pair = r2 >> 8;
    int ks = (r2 >> 7) & 1;
    int lane = (r2 >> 2) & 31;
    int w = r2 & 3;
    int g0 = lane >> 2, t = lane & 3;
    int jpar = w >> 1, wb = w & 1;
    int k = ch * 32 + ks * 16 + wb * 8 + t * 2;
    int n = pair * 16 + jpar * 8 + g0;
    const float* Wb = W + (size_t)blk * K * 128;
    float v0 = (k < K) ? Wb[(size_t)k * 128 + n] : 0.f;
    float v1 = (k + 1 < K) ? Wb[(size_t)(k + 1) * 128 + n] : 0.f;
    O[idx] = h2(v0, v1);
}

// ---------------- A loaders ----------------
__device__ __forceinline__ void loadA_g(float4* r, const float* __restrict__ A,
                                        int mBase, int k0, int M, int K, int tid) {
#pragma unroll
    for (int i = 0; i < 2; i++) {
        int q = tid + (i << 9);
        int row = q >> 3, kq = (q & 7) << 2;
        int gm = mBase + row, gk = k0 + kq;
        r[i] = make_float4(0.f, 0.f, 0.f, 0.f);
        if (gm < M && gk < K)
            r[i] = *reinterpret_cast<const float4*>(A + (size_t)gm * K + gk);
    }
}
__device__ __forceinline__ void storeA_f(uint32_t* __restrict__ buf, const float4* r, int tid) {
#pragma unroll
    for (int i4 = 0; i4 < 2; i4++) {
        int q = tid + (i4 << 9);
        int row = q >> 3, kq = (q & 7) << 2;
        int iT = row >> 4, rl = row & 15;
        int g = rl & 7, hr = rl >> 3;
        int ks = kq >> 4, kl = kq & 15;
        int w = hr + ((kl & 8) ? 2 : 0);
        int t0 = (kl & 7) >> 1;
        uint32_t* p = buf + iT * AI_STR + ks * KS_STR + (g * 4 + t0) * 4 + w;
        p[0] = h2(r[i4].x, r[i4].y);
        p[4] = h2(r[i4].z, r[i4].w);
    }
}

// ---------------- fragment loads ----------------
__device__ __forceinline__ void loadB_frag(uint4* bv, const uint32_t* __restrict__ Bg,
                                           int ch, int wid, int lane) {
    const uint32_t* Bb = Bg + ch * 2048 + ((wid >> 2) * 2) * 256 + lane * 4;
#pragma unroll
    for (int ks = 0; ks < 2; ks++)
#pragma unroll
        for (int p = 0; p < 2; p++)
            bv[ks * 2 + p] = *reinterpret_cast<const uint4*>(Bb + p * 256 + ks * 128);
}
__device__ __forceinline__ void loadAe_frag(uint4* av, const uint32_t* __restrict__ Af, int ch) {
#pragma unroll
    for (int s = 0; s < 2; s++)
#pragma unroll
        for (int i = 0; i < 2; i++)
            av[s * 2 + i] = *reinterpret_cast<const uint4*>(Af + i * 1024 + (ch * 2 + s) * 128);
}

// ---------------- mma ----------------
__device__ __forceinline__ void mma8(float c[4][4], const uint4 av, const uint4* bv) {
#pragma unroll
    for (int j = 0; j < 4; j++) {
        uint32_t b0 = (j & 1) ? bv[j >> 1].z : bv[j >> 1].x;
        uint32_t b1 = (j & 1) ? bv[j >> 1].w : bv[j >> 1].y;
        asm volatile(
            "mma.sync.aligned.m16n8k16.row.col.f32.f16.f16.f32 "
            "{%0,%1,%2,%3}, {%4,%5,%6,%7}, {%8,%9}, {%0,%1,%2,%3};\n"
            : "+f"(c[j][0]), "+f"(c[j][1]), "+f"(c[j][2]), "+f"(c[j][3])
            : "r"(av.x), "r"(av.y), "r"(av.z), "r"(av.w), "r"(b0), "r"(b1));
    }
}
__device__ __forceinline__ void mma_bv(float c[2][4][4], const uint4* aC, const uint4* bv) {
#pragma unroll
    for (int ks = 0; ks < 2; ks++)
#pragma unroll
        for (int i = 0; i < 2; i++)
            mma8(c[i], aC[ks * 2 + i], &bv[ks * 2]);
}
template<int ISTR>
__device__ __forceinline__ void mma_s_bv(const uint32_t* __restrict__ As, const uint4* bv,
                                         float c[2][4][4], int wid, int lane)
{
    const uint32_t* Ab = As + ((wid & 3) * 2) * ISTR + lane * 4;
#pragma unroll
    for (int ks = 0; ks < 2; ks++) {
        uint4 av[2];
#pragma unroll
        for (int i = 0; i < 2; i++)
            av[i] = *reinterpret_cast<const uint4*>(Ab + i * ISTR + ks * KS_STR);
#pragma unroll
        for (int i = 0; i < 2; i++)
            mma8(c[i], av[i], &bv[ks * 2]);
    }
}

__device__ __forceinline__ void zero_c(float c[2][4][4]) {
#pragma unroll
    for (int i = 0; i < 2; i++)
#pragma unroll
        for (int j = 0; j < 4; j++)
#pragma unroll
            for (int v = 0; v < 4; v++) c[i][j][v] = 0.0f;
}

__device__ __forceinline__ void store_T_frag(uint32_t* __restrict__ Tt, const float c[2][4][4],
                                             const float* bn, int wid, int g, int t,
                                             int warpN, bool doSsp)
{
    const int iTb = (wid & 3) * 2;
    const int ksBase = warpN >> 4;
#pragma unroll
    for (int i = 0; i < 2; i++)
#pragma unroll
        for (int half = 0; half < 2; half++)
#pragma unroll
            for (int j = 0; j < 4; j++) {
                float v0 = c[i][j][half * 2 + 0] + bn[j * 2 + 0];
                float v1 = c[i][j][half * 2 + 1] + bn[j * 2 + 1];
                if (doSsp) { v0 = sspf(v0); v1 = sspf(v1); }
                int ks = ksBase + (j >> 1);
                int w = half + 2 * (j & 1);
                Tt[(iTb + i) * TI_STR + ks * KS_STR + (g * 4 + t) * 4 + w] = h2(v0, v1);
            }
}

// ---------------- eattr pre-pack (gathered by compacted edge id) ------------------
__global__ void __launch_bounds__(256) pack_eattr(const float* __restrict__ ea,
                                                  uint32_t* __restrict__ out) {
    const int tile = blockIdx.x;
    if (tile * 128 >= g_nc) return;
    __shared__ uint32_t sf[8192];
    const int tid = threadIdx.x;
    const int row = tid >> 1;
    const int kh = tid & 1;
    const int eid = g_eidx[tile * 128 + row];
    const float* er = (eid >= 0) ? (ea + (size_t)eid * EC) : nullptr;
    const int iT = row >> 4, rl = row & 15;
    const int g = rl & 7, hr = rl >> 3;
#pragma unroll
    for (int q = 0; q < 4; q++) {
#pragma unroll
        for (int f4 = 0; f4 < 4; f4++) {
            int kq = kh * 64 + (q * 4 + f4) * 4;
            float4 v = make_float4(0.f, 0.f, 0.f, 0.f);
            if (er != nullptr && kq < EC) {
                if (kq + 3 < EC)
                    v = *reinterpret_cast<const float4*>(er + kq);
                else {
                    v.x = er[kq];
                    if (kq + 1 < EC) v.y = er[kq + 1];
                    if (kq + 2 < EC) v.z = er[kq + 2];
                }
            }
            int ks = kq >> 4, kl = kq & 15;
            int w = hr + ((kl & 8) ? 2 : 0);
            int t0 = (kl & 7) >> 1;
            uint32_t* p = sf + iT * 1024 + ks * 128 + (g * 4 + t0) * 4 + w;
            p[0] = h2(v.x, v.y);
            p[4] = h2(v.z, v.w);
        }
    }
    __syncthreads();
    uint32_t* o = out + (size_t)tile * 8192;
#pragma unroll
    for (int i = 0; i < 8; i++)
        *reinterpret_cast<uint4*>(o + (tid + i * 256) * 4) =
            *reinterpret_cast<const uint4*>(sf + (tid + i * 256) * 4);
}

// ---------------- fused edge kernel (compacted edges) ----------------
__global__ void __launch_bounds__(NT, 1) edge_fused(
    const uint32_t* __restrict__ eaf,
    const uint32_t* __restrict__ B1g, const float* __restrict__ b1,
    const uint32_t* __restrict__ B2g, const float* __restrict__ b2,
    const uint32_t* __restrict__ xh, float* __restrict__ agg)
{
    const int nC = g_nc;
    const int mBase = blockIdx.x * 128;
    if (mBase >= nC) return;

    extern __shared__ uint32_t sm[];
    uint32_t* Tt = sm;

    const int tid = threadIdx.x;
    const int wid = tid >> 5, lane = tid & 31;
    const int g = lane >> 2, t = lane & 3;
    const int warpM = (wid & 3) * 32, warpN = (wid >> 2) * 32;

    float c[2][4][4];
    zero_c(c);

    // stage 1: all-register, fully pipelined (A and B prefetch)
    const uint32_t* Af = eaf + (size_t)blockIdx.x * 8192 + ((wid & 3) * 2) * 1024 + lane * 4;
    uint4 aC[4], bv[4], aN[4], bN[4];
    loadAe_frag(aC, Af, 0);
    loadB_frag(bv, B1g, 0, wid, lane);
#pragma unroll
    for (int ch = 0; ch < 4; ch++) {
        if (ch < 3) {
            loadAe_frag(aN, Af, ch + 1);
            loadB_frag(bN, B1g, ch + 1, wid, lane);
        }
        mma_bv(c, aC, bv);
        if (ch < 3) {
#pragma unroll
            for (int q = 0; q < 4; q++) { aC[q] = aN[q]; bv[q] = bN[q]; }
        }
    }

    float bn1[8];
#pragma unroll
    for (int j = 0; j < 4; j++) {
        bn1[j * 2 + 0] = __ldg(b1 + warpN + j * 8 + t * 2 + 0);
        bn1[j * 2 + 1] = __ldg(b1 + warpN + j * 8 + t * 2 + 1);
    }
    store_T_frag(Tt, c, bn1, wid, g, t, warpN, true);
    zero_c(c);

    // prefetch epilogue metadata (hidden under stage 2)
    int s4[4], d4[4];
#pragma unroll
    for (int i = 0; i < 2; i++)
#pragma unroll
        for (int half = 0; half < 2; half++) {
            const int e = mBase + warpM + i * 16 + g + half * 8;
            s4[i * 2 + half] = __ldg(g_srcC + e);
            d4[i * 2 + half] = __ldg(g_dstC + e);
        }

    loadB_frag(bv, B2g, 0, wid, lane);
    __syncthreads();   // T visible to all warps

    // stage 2: T (smem) @ B2, B pipelined
#pragma unroll
    for (int ch = 0; ch < 4; ch++) {
        if (ch < 3) loadB_frag(bN, B2g, ch + 1, wid, lane);
        mma_s_bv<TI_STR>(Tt + ch * 2 * KS_STR, bv, c, wid, lane);
        if (ch < 3) {
#pragma unroll
            for (int q = 0; q < 4; q++) bv[q] = bN[q];
        }
    }

    // scatter epilogue: all compacted edges valid; guard only the tail tile
    float bn2[8];
#pragma unroll
    for (int j = 0; j < 4; j++) {
        bn2[j * 2 + 0] = __ldg(b2 + warpN + j * 8 + t * 2 + 0);
        bn2[j * 2 + 1] = __ldg(b2 + warpN + j * 8 + t * 2 + 1);
    }
#pragma unroll
    for (int i = 0; i < 2; i++)
#pragma unroll
        for (int half = 0; half < 2; half++) {
            const int e = mBase + warpM + i * 16 + g + half * 8;
            if (e < nC) {
                const uint32_t* xr = xh + (size_t)s4[i * 2 + half] * 64;
                float* ar = agg + (size_t)d4[i * 2 + half] * 128;
#pragma unroll
                for (int j = 0; j < 4; j++) {
                    const int col = warpN + j * 8 + t * 2;
                    uint32_t xw = __ldg(xr + (col >> 1));
                    float2 xv = __half22float2(*reinterpret_cast<const __half2*>(&xw));
                    float w0 = c[i][j][half * 2 + 0] + bn2[j * 2 + 0];
                    float w1 = c[i][j][half * 2 + 1] + bn2[j * 2 + 1];
                    float m0 = xv.x * w0, m1 = xv.y * w1;
                    asm volatile("red.global.add.v2.f32 [%0], {%1, %2};"
                                 :: "l"(ar + col), "f"(m0), "f"(m1) : "memory");
                }
            }
        }
}

// ---------------- fused node kernel ----------------
__global__ void __launch_bounds__(NT, 1) node_fused(
    const float* __restrict__ agg,
    const uint32_t* __restrict__ B1g, const float* __restrict__ b1,
    const uint32_t* __restrict__ B2g, const float* __restrict__ b2,
    float* __restrict__ h, const uint32_t* __restrict__ B3g, uint32_t* __restrict__ xOut)
{
    extern __shared__ uint32_t sm[];
    uint32_t* Tt  = sm;
    uint32_t* As0 = sm + TWORDS;
    uint32_t* As1 = As0 + AWORDS;

    const int tid = threadIdx.x;
    const int wid = tid >> 5, lane = tid & 31;
    const int g = lane >> 2, t = lane & 3;
    const int warpM = (wid & 3) * 32, warpN = (wid >> 2) * 32;
    const int mBase = blockIdx.x * 128;

    float c[2][4][4];
    zero_c(c);
    float4 aR[2];
    uint4 bv[4], bN[4];

    // stage 1: agg (smem-staged A, double-buffered) @ B1 (B pipelined)
    loadA_g(aR, agg, mBase, 0, N_NODES, 128, tid);
    loadB_frag(bv, B1g, 0, wid, lane);
    storeA_f(As0, aR, tid);
    __syncthreads();
#pragma unroll
    for (int ch = 0; ch < 4; ch++) {
        if (ch < 3) {
            loadA_g(aR, agg, mBase, (ch + 1) * 32, N_NODES, 128, tid);
            loadB_frag(bN, B1g, ch + 1, wid, lane);
        }
        mma_s_bv<AI_STR>((ch & 1) ? As1 : As0, bv, c, wid, lane);
        if (ch < 3) {
            storeA_f(((ch + 1) & 1) ? As1 : As0, aR, tid);
#pragma unroll
            for (int q = 0; q < 4; q++) bv[q] = bN[q];
        }
        __syncthreads();
    }

    float bn1[8];
#pragma unroll
    for (int j = 0; j < 4; j++) {
        bn1[j * 2 + 0] = __ldg(b1 + warpN + j * 8 + t * 2 + 0);
        bn1[j * 2 + 1] = __ldg(b1 + warpN + j * 8 + t * 2 + 1);
    }
    store_T_frag(Tt, c, bn1, wid, g, t, warpN, true);
    zero_c(c);
    loadB_frag(bv, B2g, 0, wid, lane);
    __syncthreads();

    // stage 2: T @ B2 (B pipelined)
#pragma unroll
    for (int ch = 0; ch < 4; ch++) {
        if (ch < 3) loadB_frag(bN, B2g, ch + 1, wid, lane);
        mma_s_bv<TI_STR>(Tt + ch * 2 * KS_STR, bv, c, wid, lane);
        if (ch < 3) {
#pragma unroll
            for (int q = 0; q < 4; q++) bv[q] = bN[q];
        }
    }
    __syncthreads();   // all warps done reading Tt before epilogue overwrites it

    // stage-2 epilogue: h += residual; keep hnew resident in T-frag
    float bn2[8];
#pragma unroll
    for (int j = 0; j < 4; j++) {
        bn2[j * 2 + 0] = __ldg(b2 + warpN + j * 8 + t * 2 + 0);
        bn2[j * 2 + 1] = __ldg(b2 + warpN + j * 8 + t * 2 + 1);
    }
    const int iTb = (wid & 3) * 2;
    const int ksBase = warpN >> 4;
#pragma unroll
    for (int i = 0; i < 2; i++)
#pragma unroll
        for (int half = 0; half < 2; half++) {
            const int gm = mBase + warpM + i * 16 + g + half * 8;
            const bool ok = gm < N_NODES;
            float* hrow = h + (size_t)gm * 128;
#pragma unroll
            for (int j = 0; j < 4; j++) {
                const int col = warpN + j * 8 + t * 2;
                float v0 = c[i][j][half * 2 + 0] + bn2[j * 2 + 0];
                float v1 = c[i][j][half * 2 + 1] + bn2[j * 2 + 1];
                if (ok) {
                    float2 hv = *reinterpret_cast<const float2*>(hrow + col);
                    v0 += hv.x; v1 += hv.y;
                    *reinterpret_cast<float2*>(hrow + col) = make_float2(v0, v1);
                }
                int ks = ksBase + (j >> 1);
                int w = half + 2 * (j & 1);
                Tt[(iTb + i) * TI_STR + ks * KS_STR + (g * 4 + t) * 4 + w] = h2(v0, v1);
            }
        }

    // stage 3: xOut(half2) = hnew @ lin1next (B pipelined)
    if (B3g != nullptr) {
        zero_c(c);
        loadB_frag(bv, B3g, 0, wid, lane);
        __syncthreads();   // hnew T-frag complete
#pragma unroll
        for (int ch = 0; ch < 4; ch++) {
            if (ch < 3) loadB_frag(bN, B3g, ch + 1, wid, lane);
            mma_s_bv<TI_STR>(Tt + ch * 2 * KS_STR, bv, c, wid, lane);
            if (ch < 3) {
#pragma unroll
                for (int q = 0; q < 4; q++) bv[q] = bN[q];
            }
        }
#pragma unroll
        for (int i = 0; i < 2; i++)
#pragma unroll
            for (int half = 0; half < 2; half++) {
                const int gm = mBase + warpM + i * 16 + g + half * 8;
                if (gm < N_NODES) {
                    uint32_t* orow = xOut + (size_t)gm * 64;
#pragma unroll
                    for (int j = 0; j < 4; j++) {
                        const int col = warpN + j * 8 + t * 2;
                        orow[col >> 1] = h2(c[i][j][half * 2 + 0], c[i][j][half * 2 + 1]);
                    }
                }
            }
    }
}

// ---------------- plain GEMM (initial x = h @ lin1_0, half2 out) ------------------
__global__ void __launch_bounds__(NT, 1) gemm_plain(
    const float* __restrict__ A, const uint32_t* __restrict__ Bg,
    uint32_t* __restrict__ out, int M)
{
    extern __shared__ uint32_t sm[];
    uint32_t* As0 = sm;
    uint32_t* As1 = As0 + AWORDS;

    const int tid = threadIdx.x;
    const int wid = tid >> 5, lane = tid & 31;
    const int g = lane >> 2, t = lane & 3;
    const int warpM = (wid & 3) * 32, warpN = (wid >> 2) * 32;
    const int mBase = blockIdx.x * 128;

    float c[2][4][4];
    zero_c(c);
    float4 aR[2];
    uint4 bv[4], bN[4];
    loadA_g(aR, A, mBase, 0, M, 128, tid);
    loadB_frag(bv, Bg, 0, wid, lane);
    storeA_f(As0, aR, tid);
    __syncthreads();
#pragma unroll
    for (int ch = 0; ch < 4; ch++) {
        if (ch < 3) {
            loadA_g(aR, A, mBase, (ch + 1) * 32, M, 128, tid);
            loadB_frag(bN, Bg, ch + 1, wid, lane);
        }
        mma_s_bv<AI_STR>((ch & 1) ? As1 : As0, bv, c, wid, lane);
        if (ch < 3) {
            storeA_f(((ch + 1) & 1) ? As1 : As0, aR, tid);
#pragma unroll
            for (int q = 0; q < 4; q++) bv[q] = bN[q];
        }
        __syncthreads();
    }
#pragma unroll
    for (int i = 0; i < 2; i++)
#pragma unroll
        for (int half = 0; half < 2; half++) {
            const int gm = mBase + warpM + i * 16 + g + half * 8;
            if (gm < M) {
                uint32_t* orow = out + (size_t)gm * 64;
#pragma unroll
                for (int j = 0; j < 4; j++) {
                    const int col = warpN + j * 8 + t * 2;
                    orow[col >> 1] = h2(c[i][j][half * 2 + 0], c[i][j][half * 2 + 1]);
                }
            }
        }
}

// ---------------- small kernels ----------------
__global__ void embed_kernel(const float* __restrict__ z, const float* __restrict__ w,
                             const float* __restrict__ b, float* __restrict__ h) {
    int n = blockIdx.x, j = threadIdx.x;
    const float* zr = z + (size_t)n * (IN_DIM + HID);
    float acc = b[j] + zr[IN_DIM + j];
#pragma unroll
    for (int k = 0; k < IN_DIM; k++) acc = fmaf(zr[k], w[k * HID + j], acc);
    h[(size_t)n * HID + j] = acc;
}

__global__ void zero_kernel(float4* __restrict__ p, int n4) {
    int i = blockIdx.x * 256 + threadIdx.x;
    if (i < n4) p[i] = make_float4(0.f, 0.f, 0.f, 0.f);
}

// ---------------- host launch ----------------
extern "C" void kernel_launch(void* const* d_in, const int* in_sizes, int n_in,
                              void* d_out, int out_size) {
    const float* z      = (const float*)d_in[0];
    const int*   ei     = (const int*)  d_in[1];
    const float* elen   = (const float*)d_in[2];
    const float* eattr  = (const float*)d_in[3];
    const float* emb_w  = (const float*)d_in[4];
    const float* emb_b  = (const float*)d_in[5];
    const float* lin1_w = (const float*)d_in[6];
    const float* nn_w1  = (const float*)d_in[7];
    const float* nn_b1  = (const float*)d_in[8];
    const float* nn_w2  = (const float*)d_in[9];
    const float* nn_b2  = (const float*)d_in[10];
    const float* lin2_w = (const float*)d_in[11];
    const float* lin2_b = (const float*)d_in[12];
    const float* lin_w  = (const float*)d_in[13];
    const float* lin_b  = (const float*)d_in[14];
    float* h = (float*)d_out;

    float* pagg;
    uint32_t *pxh, *peaf, *pw1, *pw2, *pl2, *pl, *pl1;
    cudaGetSymbolAddress((void**)&pxh,  g_xh);
    cudaGetSymbolAddress((void**)&pagg, g_agg);
    cudaGetSymbolAddress((void**)&peaf, g_eaf);
    cudaGetSymbolAddress((void**)&pw1,  g_w1f);
    cudaGetSymbolAddress((void**)&pw2,  g_w2f);
    cudaGetSymbolAddress((void**)&pl2,  g_l2f);
    cudaGetSymbolAddress((void**)&pl,   g_lf);
    cudaGetSymbolAddress((void**)&pl1,  g_l1f);

    cudaFuncSetAttribute(edge_fused, cudaFuncAttributeMaxDynamicSharedMemorySize, EDGE_SMEM);
    cudaFuncSetAttribute(node_fused, cudaFuncAttributeMaxDynamicSharedMemorySize, NODE_SMEM);
    cudaFuncSetAttribute(gemm_plain, cudaFuncAttributeMaxDynamicSharedMemorySize, PLAIN_SMEM);

    const int* src = ei;
    const int* dst = ei + N_EDGES;

    embed_kernel<<<N_NODES, HID>>>(z, emb_w, emb_b, h);
    // edge compaction
    count_kernel<<<NBLK_C, 256>>>(elen);
    scan_kernel<<<1, 1024>>>();
    scatter_kernel<<<NBLK_C, 256>>>(elen, src, dst);
    pad_kernel<<<NBLK_C, 256>>>();
    pack_eattr<<<NTILES, 256>>>(eattr, peaf);
    {
        dim3 gw((6 * 8192 + 255) / 256, 5);
        pack_w<<<gw, 256>>>(nn_w1, nn_w2, lin2_w, lin_w, lin1_w, pw1, pw2, pl2, pl, pl1);
    }

    const int nodeTiles = (N_NODES + 127) / 128;   // 391
    const int aggN4 = N_NODES * HID / 4;

    gemm_plain<<<nodeTiles, NT, PLAIN_SMEM>>>(h, pl1, pxh, N_NODES);

    for (int i = 0; i < N_BLOCKS; i++) {
        zero_kernel<<<(aggN4 + 255) / 256, 256>>>((float4*)pagg, aggN4);
        edge_fused<<<NTILES, NT, EDGE_SMEM>>>(
            peaf, pw1 + i * 8192, nn_b1 + (size_t)i * HID,
            pw2 + i * 8192, nn_b2 + (size_t)i * HID,
            pxh, pagg);
        const uint32_t* lin1next = (i + 1 < N_BLOCKS) ? (pl1 + (i + 1) * 8192) : nullptr;
        node_fused<<<nodeTiles, NT, NODE_SMEM>>>(
            pagg, pl2 + i * 8192, lin2_b + (size_t)i * HID,
            pl + i * 8192, lin_b + (size_t)i * HID,
            h, lin1next, pxh);
    }
}

// round 13
// speedup vs baseline: 1.2337x; 1.2337x over previous
#include <cuda_runtime.h>
#include <cuda_fp16.h>
#include <cstdint>
#include <math.h>

#define N_NODES 50000
#define N_EDGES 800000
#define HID 128
#define EC 100
#define IN_DIM 5
#define N_BLOCKS 6
#define NT 512
#define NTILES 6250

// ---------------- scratch (device globals; no runtime allocation) ----------------
__device__ uint32_t g_xh[N_NODES * 64];        // x in half2 (12.8 MB)
__device__ float g_agg[N_NODES * HID];
__device__ float g_C[N_EDGES];
__device__ uint32_t g_eaf[(size_t)NTILES * 8192];   // eattr fragment-order fp16
__device__ uint32_t g_w1f[6 * 8192];
__device__ uint32_t g_w2f[6 * 8192];
__device__ uint32_t g_l2f[6 * 8192];
__device__ uint32_t g_lf [6 * 8192];
__device__ uint32_t g_l1f[6 * 8192];

__device__ __forceinline__ float sspf(float x) {
    float sp = fmaxf(x, 0.0f) + log1pf(expf(-fabsf(x)));
    return sp - 0.69314718055994531f;
}
__device__ __forceinline__ uint32_t h2(float lo, float hi) {
    uint32_t r;
    asm("cvt.rn.f16x2.f32 %0, %1, %2;" : "=r"(r) : "f"(hi), "f"(lo));
    return r;
}

// ---------------- fragment layout constants ----------------
#define KS_STR 132
#define AI_STR 264
#define AWORDS 2112
#define TI_STR 1056
#define TWORDS 8448

#define EDGE_SMEM (TWORDS * 4)
#define NODE_SMEM ((TWORDS + 2 * AWORDS) * 4)
#define PLAIN_SMEM ((2 * AWORDS) * 4)

// ---------------- weight pre-pack ----------------
__global__ void __launch_bounds__(256) pack_w(
    const float* __restrict__ w1, const float* __restrict__ w2,
    const float* __restrict__ l2, const float* __restrict__ l,
    const float* __restrict__ l1,
    uint32_t* __restrict__ o1, uint32_t* __restrict__ o2,
    uint32_t* __restrict__ o3, uint32_t* __restrict__ o4,
    uint32_t* __restrict__ o5)
{
    const float* W; uint32_t* O; int K;
    switch (blockIdx.y) {
        case 0: W = w1; O = o1; K = EC;  break;
        case 1: W = w2; O = o2; K = 128; break;
        case 2: W = l2; O = o3; K = 128; break;
        case 3: W = l;  O = o4; K = 128; break;
        default: W = l1; O = o5; K = 128; break;
    }
    int idx = blockIdx.x * 256 + threadIdx.x;
    if (idx >= 6 * 8192) return;
    int blk = idx >> 13;
    int r = idx & 8191;
    int ch = r >> 11;
    int r2 = r & 2047;
    int pair = r2 >> 8;
    int ks = (r2 >> 7) & 1;
    int lane = (r2 >> 2) & 31;
    int w = r2 & 3;
    int g0 = lane >> 2, t = lane & 3;
    int jpar = w >> 1, wb = w & 1;
    int k = ch * 32 + ks * 16 + wb * 8 + t * 2;
    int n = pair * 16 + jpar * 8 + g0;
    const float* Wb = W + (size_t)blk * K * 128;
    float v0 = (k < K) ? Wb[(size_t)k * 128 + n] : 0.f;
    float v1 = (k + 1 < K) ? Wb[(size_t)(k + 1) * 128 + n] : 0.f;
    O[idx] = h2(v0, v1);
}

// ---------------- A loaders ----------------
__device__ __forceinline__ void loadA_g(float4* r, const float* __restrict__ A,
                                        int mBase, int k0, int M, int K, int tid) {
#pragma unroll
    for (int i = 0; i < 2; i++) {
        int q = tid + (i << 9);
        int row = q >> 3, kq = (q & 7) << 2;
        int gm = mBase + row, gk = k0 + kq;
        r[i] = make_float4(0.f, 0.f, 0.f, 0.f);
        if (gm < M && gk < K)
            r[i] = *reinterpret_cast<const float4*>(A + (size_t)gm * K + gk);
    }
}
__device__ __forceinline__ void storeA_f(uint32_t* __restrict__ buf, const float4* r, int tid) {
#pragma unroll
    for (int i4 = 0; i4 < 2; i4++) {
        int q = tid + (i4 << 9);
        int row = q >> 3, kq = (q & 7) << 2;
        int iT = row >> 4, rl = row & 15;
        int g = rl & 7, hr = rl >> 3;
        int ks = kq >> 4, kl = kq & 15;
        int w = hr + ((kl & 8) ? 2 : 0);
        int t0 = (kl & 7) >> 1;
        uint32_t* p = buf + iT * AI_STR + ks * KS_STR + (g * 4 + t0) * 4 + w;
        p[0] = h2(r[i4].x, r[i4].y);
        p[4] = h2(r[i4].z, r[i4].w);
    }
}

// ---------------- fragment loads ----------------
__device__ __forceinline__ void loadB_frag(uint4* bv, const uint32_t* __restrict__ Bg,
                                           int ch, int wid, int lane) {
    const uint32_t* Bb = Bg + ch * 2048 + ((wid >> 2) * 2) * 256 + lane * 4;
#pragma unroll
    for (int ks = 0; ks < 2; ks++)
#pragma unroll
        for (int p = 0; p < 2; p++)
            bv[ks * 2 + p] = *reinterpret_cast<const uint4*>(Bb + p * 256 + ks * 128);
}
__device__ __forceinline__ void loadAe_frag(uint4* av, const uint32_t* __restrict__ Af, int ch) {
#pragma unroll
    for (int s = 0; s < 2; s++)
#pragma unroll
        for (int i = 0; i < 2; i++)
            av[s * 2 + i] = *reinterpret_cast<const uint4*>(Af + i * 1024 + (ch * 2 + s) * 128);
}

// ---------------- mma ----------------
__device__ __forceinline__ void mma8(float c[4][4], const uint4 av, const uint4* bv) {
#pragma unroll
    for (int j = 0; j < 4; j++) {
        uint32_t b0 = (j & 1) ? bv[j >> 1].z : bv[j >> 1].x;
        uint32_t b1 = (j & 1) ? bv[j >> 1].w : bv[j >> 1].y;
        asm volatile(
            "mma.sync.aligned.m16n8k16.row.col.f32.f16.f16.f32 "
            "{%0,%1,%2,%3}, {%4,%5,%6,%7}, {%8,%9}, {%0,%1,%2,%3};\n"
            : "+f"(c[j][0]), "+f"(c[j][1]), "+f"(c[j][2]), "+f"(c[j][3])
            : "r"(av.x), "r"(av.y), "r"(av.z), "r"(av.w), "r"(b0), "r"(b1));
    }
}
__device__ __forceinline__ void mma_bv(float c[2][4][4], const uint4* aC, const uint4* bv) {
#pragma unroll
    for (int ks = 0; ks < 2; ks++)
#pragma unroll
        for (int i = 0; i < 2; i++)
            mma8(c[i], aC[ks * 2 + i], &bv[ks * 2]);
}
template<int ISTR>
__device__ __forceinline__ void mma_s_bv(const uint32_t* __restrict__ As, const uint4* bv,
                                         float c[2][4][4], int wid, int lane)
{
    const uint32_t* Ab = As + ((wid & 3) * 2) * ISTR + lane * 4;
#pragma unroll
    for (int ks = 0; ks < 2; ks++) {
        uint4 av[2];
#pragma unroll
        for (int i = 0; i < 2; i++)
            av[i] = *reinterpret_cast<const uint4*>(Ab + i * ISTR + ks * KS_STR);
#pragma unroll
        for (int i = 0; i < 2; i++)
            mma8(c[i], av[i], &bv[ks * 2]);
    }
}

__device__ __forceinline__ void zero_c(float c[2][4][4]) {
#pragma unroll
    for (int i = 0; i < 2; i++)
#pragma unroll
        for (int j = 0; j < 4; j++)
#pragma unroll
            for (int v = 0; v < 4; v++) c[i][j][v] = 0.0f;
}

__device__ __forceinline__ void store_T_frag(uint32_t* __restrict__ Tt, const float c[2][4][4],
                                             const float* bn, int wid, int g, int t,
                                             int warpN, bool doSsp)
{
    const int iTb = (wid & 3) * 2;
    const int ksBase = warpN >> 4;
#pragma unroll
    for (int i = 0; i < 2; i++)
#pragma unroll
        for (int half = 0; half < 2; half++)
#pragma unroll
            for (int j = 0; j < 4; j++) {
                float v0 = c[i][j][half * 2 + 0] + bn[j * 2 + 0];
                float v1 = c[i][j][half * 2 + 1] + bn[j * 2 + 1];
                if (doSsp) { v0 = sspf(v0); v1 = sspf(v1); }
                int ks = ksBase + (j >> 1);
                int w = half + 2 * (j & 1);
                Tt[(iTb + i) * TI_STR + ks * KS_STR + (g * 4 + t) * 4 + w] = h2(v0, v1);
            }
}

// ---------------- eattr pre-pack (tile-staged, coalesced; proven R9/R11) ----------
__global__ void __launch_bounds__(256) pack_eattr(const float* __restrict__ ea,
                                                  uint32_t* __restrict__ out) {
    __shared__ uint32_t sf[8192];
    const int tile = blockIdx.x;
    const int tid = threadIdx.x;
    const int row = tid >> 1;
    const int kh = tid & 1;
    const float* er = ea + ((size_t)tile * 128 + row) * EC;
    const int iT = row >> 4, rl = row & 15;
    const int g = rl & 7, hr = rl >> 3;
#pragma unroll
    for (int q = 0; q < 4; q++) {
#pragma unroll
        for (int f4 = 0; f4 < 4; f4++) {
            int kq = kh * 64 + (q * 4 + f4) * 4;
            float4 v = make_float4(0.f, 0.f, 0.f, 0.f);
            if (kq < EC) {
                if (kq + 3 < EC)
                    v = *reinterpret_cast<const float4*>(er + kq);
                else {
                    v.x = er[kq];
                    if (kq + 1 < EC) v.y = er[kq + 1];
                    if (kq + 2 < EC) v.z = er[kq + 2];
                }
            }
            int ks = kq >> 4, kl = kq & 15;
            int w = hr + ((kl & 8) ? 2 : 0);
            int t0 = (kl & 7) >> 1;
            uint32_t* p = sf + iT * 1024 + ks * 128 + (g * 4 + t0) * 4 + w;
            p[0] = h2(v.x, v.y);
            p[4] = h2(v.z, v.w);
        }
    }
    __syncthreads();
    uint32_t* o = out + (size_t)tile * 8192;
#pragma unroll
    for (int i = 0; i < 8; i++)
        *reinterpret_cast<uint4*>(o + (tid + i * 256) * 4) =
            *reinterpret_cast<const uint4*>(sf + (tid + i * 256) * 4);
}

// ---------------- fused edge kernel ----------------
__global__ void __launch_bounds__(NT, 1) edge_fused(
    const uint32_t* __restrict__ eaf,
    const uint32_t* __restrict__ B1g, const float* __restrict__ b1,
    const uint32_t* __restrict__ B2g, const float* __restrict__ b2,
    const float* __restrict__ Cm, const int* __restrict__ src, const int* __restrict__ dst,
    const uint32_t* __restrict__ xh, float* __restrict__ agg)
{
    extern __shared__ uint32_t sm[];
    uint32_t* Tt = sm;

    const int tid = threadIdx.x;
    const int wid = tid >> 5, lane = tid & 31;
    const int g = lane >> 2, t = lane & 3;
    const int warpM = (wid & 3) * 32, warpN = (wid >> 2) * 32;
    const int mBase = blockIdx.x * 128;

    float c[2][4][4];
    zero_c(c);

    // stage 1: all-register, fully pipelined (A and B prefetch)
    const uint32_t* Af = eaf + (size_t)blockIdx.x * 8192 + ((wid & 3) * 2) * 1024 + lane * 4;
    uint4 aC[4], bv[4], aN[4], bN[4];
    loadAe_frag(aC, Af, 0);
    loadB_frag(bv, B1g, 0, wid, lane);
#pragma unroll
    for (int ch = 0; ch < 4; ch++) {
        if (ch < 3) {
            loadAe_frag(aN, Af, ch + 1);
            loadB_frag(bN, B1g, ch + 1, wid, lane);
        }
        mma_bv(c, aC, bv);
        if (ch < 3) {
#pragma unroll
            for (int q = 0; q < 4; q++) { aC[q] = aN[q]; bv[q] = bN[q]; }
        }
    }

    float bn1[8];
#pragma unroll
    for (int j = 0; j < 4; j++) {
        bn1[j * 2 + 0] = __ldg(b1 + warpN + j * 8 + t * 2 + 0);
        bn1[j * 2 + 1] = __ldg(b1 + warpN + j * 8 + t * 2 + 1);
    }
    store_T_frag(Tt, c, bn1, wid, g, t, warpN, true);
    zero_c(c);

    // prefetch epilogue metadata (hidden under stage 2)
    float cmv4[4]; int s4[4], d4[4];
#pragma unroll
    for (int i = 0; i < 2; i++)
#pragma unroll
        for (int half = 0; half < 2; half++) {
            const int e = mBase + warpM + i * 16 + g + half * 8;
            cmv4[i * 2 + half] = __ldg(Cm + e);
            s4[i * 2 + half] = __ldg(src + e);
            d4[i * 2 + half] = __ldg(dst + e);
        }

    loadB_frag(bv, B2g, 0, wid, lane);
    __syncthreads();   // T visible to all warps

    // stage 2: T (smem) @ B2, B pipelined
#pragma unroll
    for (int ch = 0; ch < 4; ch++) {
        if (ch < 3) loadB_frag(bN, B2g, ch + 1, wid, lane);
        mma_s_bv<TI_STR>(Tt + ch * 2 * KS_STR, bv, c, wid, lane);
        if (ch < 3) {
#pragma unroll
            for (int q = 0; q < 4; q++) bv[q] = bN[q];
        }
    }

    // scatter epilogue: guarded red.global.add.v2.f32, x gathered as half2
    float bn2[8];
#pragma unroll
    for (int j = 0; j < 4; j++) {
        bn2[j * 2 + 0] = __ldg(b2 + warpN + j * 8 + t * 2 + 0);
        bn2[j * 2 + 1] = __ldg(b2 + warpN + j * 8 + t * 2 + 1);
    }
#pragma unroll
    for (int i = 0; i < 2; i++)
#pragma unroll
        for (int half = 0; half < 2; half++) {
            const float cmv = cmv4[i * 2 + half];
            if (cmv != 0.0f) {
                const uint32_t* xr = xh + (size_t)s4[i * 2 + half] * 64;
                float* ar = agg + (size_t)d4[i * 2 + half] * 128;
#pragma unroll
                for (int j = 0; j < 4; j++) {
                    const int col = warpN + j * 8 + t * 2;
                    uint32_t xw = __ldg(xr + (col >> 1));
                    float2 xv = __half22float2(*reinterpret_cast<const __half2*>(&xw));
                    float w0 = (c[i][j][half * 2 + 0] + bn2[j * 2 + 0]) * cmv;
                    float w1 = (c[i][j][half * 2 + 1] + bn2[j * 2 + 1]) * cmv;
                    float m0 = xv.x * w0, m1 = xv.y * w1;
                    asm volatile("red.global.add.v2.f32 [%0], {%1, %2};"
                                 :: "l"(ar + col), "f"(m0), "f"(m1) : "memory");
                }
            }
        }
}

// ---------------- fused node kernel ----------------
__global__ void __launch_bounds__(NT, 1) node_fused(
    const float* __restrict__ agg,
    const uint32_t* __restrict__ B1g, const float* __restrict__ b1,
    const uint32_t* __restrict__ B2g, const float* __restrict__ b2,
    float* __restrict__ h, const uint32_t* __restrict__ B3g, uint32_t* __restrict__ xOut)
{
    extern __shared__ uint32_t sm[];
    uint32_t* Tt  = sm;
    uint32_t* As0 = sm + TWORDS;
    uint32_t* As1 = As0 + AWORDS;

    const int tid = threadIdx.x;
    const int wid = tid >> 5, lane = tid & 31;
    const int g = lane >> 2, t = lane & 3;
    const int warpM = (wid & 3) * 32, warpN = (wid >> 2) * 32;
    const int mBase = blockIdx.x * 128;

    float c[2][4][4];
    zero_c(c);
    float4 aR[2];
    uint4 bv[4], bN[4];

    // stage 1: agg (smem-staged A, double-buffered) @ B1 (B pipelined)
    loadA_g(aR, agg, mBase, 0, N_NODES, 128, tid);
    loadB_frag(bv, B1g, 0, wid, lane);
    storeA_f(As0, aR, tid);
    __syncthreads();
#pragma unroll
    for (int ch = 0; ch < 4; ch++) {
        if (ch < 3) {
            loadA_g(aR, agg, mBase, (ch + 1) * 32, N_NODES, 128, tid);
            loadB_frag(bN, B1g, ch + 1, wid, lane);
        }
        mma_s_bv<AI_STR>((ch & 1) ? As1 : As0, bv, c, wid, lane);
        if (ch < 3) {
            storeA_f(((ch + 1) & 1) ? As1 : As0, aR, tid);
#pragma unroll
            for (int q = 0; q < 4; q++) bv[q] = bN[q];
        }
        __syncthreads();
    }

    float bn1[8];
#pragma unroll
    for (int j = 0; j < 4; j++) {
        bn1[j * 2 + 0] = __ldg(b1 + warpN + j * 8 + t * 2 + 0);
        bn1[j * 2 + 1] = __ldg(b1 + warpN + j * 8 + t * 2 + 1);
    }
    store_T_frag(Tt, c, bn1, wid, g, t, warpN, true);
    zero_c(c);
    loadB_frag(bv, B2g, 0, wid, lane);
    __syncthreads();

    // stage 2: T @ B2 (B pipelined)
#pragma unroll
    for (int ch = 0; ch < 4; ch++) {
        if (ch < 3) loadB_frag(bN, B2g, ch + 1, wid, lane);
        mma_s_bv<TI_STR>(Tt + ch * 2 * KS_STR, bv, c, wid, lane);
        if (ch < 3) {
#pragma unroll
            for (int q = 0; q < 4; q++) bv[q] = bN[q];
        }
    }
    __syncthreads();   // all warps done reading Tt before epilogue overwrites it

    // stage-2 epilogue: h += residual; keep hnew resident in T-frag
    float bn2[8];
#pragma unroll
    for (int j = 0; j < 4; j++) {
        bn2[j * 2 + 0] = __ldg(b2 + warpN + j * 8 + t * 2 + 0);
        bn2[j * 2 + 1] = __ldg(b2 + warpN + j * 8 + t * 2 + 1);
    }
    const int iTb = (wid & 3) * 2;
    const int ksBase = warpN >> 4;
#pragma unroll
    for (int i = 0; i < 2; i++)
#pragma unroll
        for (int half = 0; half < 2; half++) {
            const int gm = mBase + warpM + i * 16 + g + half * 8;
            const bool ok = gm < N_NODES;
            float* hrow = h + (size_t)gm * 128;
#pragma unroll
            for (int j = 0; j < 4; j++) {
                const int col = warpN + j * 8 + t * 2;
                float v0 = c[i][j][half * 2 + 0] + bn2[j * 2 + 0];
                float v1 = c[i][j][half * 2 + 1] + bn2[j * 2 + 1];
                if (ok) {
                    float2 hv = *reinterpret_cast<const float2*>(hrow + col);
                    v0 += hv.x; v1 += hv.y;
                    *reinterpret_cast<float2*>(hrow + col) = make_float2(v0, v1);
                }
                int ks = ksBase + (j >> 1);
                int w = half + 2 * (j & 1);
                Tt[(iTb + i) * TI_STR + ks * KS_STR + (g * 4 + t) * 4 + w] = h2(v0, v1);
            }
        }

    // stage 3: xOut(half2) = hnew @ lin1next (B pipelined)
    if (B3g != nullptr) {
        zero_c(c);
        loadB_frag(bv, B3g, 0, wid, lane);
        __syncthreads();   // hnew T-frag complete
#pragma unroll
        for (int ch = 0; ch < 4; ch++) {
            if (ch < 3) loadB_frag(bN, B3g, ch + 1, wid, lane);
            mma_s_bv<TI_STR>(Tt + ch * 2 * KS_STR, bv, c, wid, lane);
            if (ch < 3) {
#pragma unroll
                for (int q = 0; q < 4; q++) bv[q] = bN[q];
            }
        }
#pragma unroll
        for (int i = 0; i < 2; i++)
#pragma unroll
            for (int half = 0; half < 2; half++) {
                const int gm = mBase + warpM + i * 16 + g + half * 8;
                if (gm < N_NODES) {
                    uint32_t* orow = xOut + (size_t)gm * 64;
#pragma unroll
                    for (int j = 0; j < 4; j++) {
                        const int col = warpN + j * 8 + t * 2;
                        orow[col >> 1] = h2(c[i][j][half * 2 + 0], c[i][j][half * 2 + 1]);
                    }
                }
            }
    }
}

// ---------------- plain GEMM (initial x = h @ lin1_0, half2 out) ------------------
__global__ void __launch_bounds__(NT, 1) gemm_plain(
    const float* __restrict__ A, const uint32_t* __restrict__ Bg,
    uint32_t* __restrict__ out, int M)
{
    extern __shared__ uint32_t sm[];
    uint32_t* As0 = sm;
    uint32_t* As1 = As0 + AWORDS;

    const int tid = threadIdx.x;
    const int wid = tid >> 5, lane = tid & 31;
    const int g = lane >> 2, t = lane & 3;
    const int warpM = (wid & 3) * 32, warpN = (wid >> 2) * 32;
    const int mBase = blockIdx.x * 128;

    float c[2][4][4];
    zero_c(c);
    float4 aR[2];
    uint4 bv[4], bN[4];
    loadA_g(aR, A, mBase, 0, M, 128, tid);
    loadB_frag(bv, Bg, 0, wid, lane);
    storeA_f(As0, aR, tid);
    __syncthreads();
#pragma unroll
    for (int ch = 0; ch < 4; ch++) {
        if (ch < 3) {
            loadA_g(aR, A, mBase, (ch + 1) * 32, M, 128, tid);
            loadB_frag(bN, Bg, ch + 1, wid, lane);
        }
        mma_s_bv<AI_STR>((ch & 1) ? As1 : As0, bv, c, wid, lane);
        if (ch < 3) {
            storeA_f(((ch + 1) & 1) ? As1 : As0, aR, tid);
#pragma unroll
            for (int q = 0; q < 4; q++) bv[q] = bN[q];
        }
        __syncthreads();
    }
#pragma unroll
    for (int i = 0; i < 2; i++)
#pragma unroll
        for (int half = 0; half < 2; half++) {
            const int gm = mBase + warpM + i * 16 + g + half * 8;
            if (gm < M) {
                uint32_t* orow = out + (size_t)gm * 64;
#pragma unroll
                for (int j = 0; j < 4; j++) {
                    const int col = warpN + j * 8 + t * 2;
                    orow[col >> 1] = h2(c[i][j][half * 2 + 0], c[i][j][half * 2 + 1]);
                }
            }
        }
}

// ---------------- small kernels ----------------
__global__ void embed_kernel(const float* __restrict__ z, const float* __restrict__ w,
                             const float* __restrict__ b, float* __restrict__ h) {
    int n = blockIdx.x, j = threadIdx.x;
    const float* zr = z + (size_t)n * (IN_DIM + HID);
    float acc = b[j] + zr[IN_DIM + j];
#pragma unroll
    for (int k = 0; k < IN_DIM; k++) acc = fmaf(zr[k], w[k * HID + j], acc);
    h[(size_t)n * HID + j] = acc;
}

__global__ void cmask_kernel(const float* __restrict__ len, float* __restrict__ C) {
    int e = blockIdx.x * 256 + threadIdx.x;
    if (e < N_EDGES) {
        float l = len[e];
        C[e] = (l <= 10.0f && l >= 0.0f) ? 1.0f : 0.0f;
    }
}

__global__ void zero_kernel(float4* __restrict__ p, int n4) {
    int i = blockIdx.x * 256 + threadIdx.x;
    if (i < n4) p[i] = make_float4(0.f, 0.f, 0.f, 0.f);
}

// ---------------- host launch ----------------
extern "C" void kernel_launch(void* const* d_in, const int* in_sizes, int n_in,
                              void* d_out, int out_size) {
    const float* z      = (const float*)d_in[0];
    const int*   ei     = (const int*)  d_in[1];
    const float* elen   = (const float*)d_in[2];
    const float* eattr  = (const float*)d_in[3];
    const float* emb_w  = (const float*)d_in[4];
    const float* emb_b  = (const float*)d_in[5];
    const float* lin1_w = (const float*)d_in[6];
    const float* nn_w1  = (const float*)d_in[7];
    const float* nn_b1  = (const float*)d_in[8];
    const float* nn_w2  = (const float*)d_in[9];
    const float* nn_b2  = (const float*)d_in[10];
    const float* lin2_w = (const float*)d_in[11];
    const float* lin2_b = (const float*)d_in[12];
    const float* lin_w  = (const float*)d_in[13];
    const float* lin_b  = (const float*)d_in[14];
    float* h = (float*)d_out;

    float *pagg, *pC;
    uint32_t *pxh, *peaf, *pw1, *pw2, *pl2, *pl, *pl1;
    cudaGetSymbolAddress((void**)&pxh,  g_xh);
    cudaGetSymbolAddress((void**)&pagg, g_agg);
    cudaGetSymbolAddress((void**)&pC,   g_C);
    cudaGetSymbolAddress((void**)&peaf, g_eaf);
    cudaGetSymbolAddress((void**)&pw1,  g_w1f);
    cudaGetSymbolAddress((void**)&pw2,  g_w2f);
    cudaGetSymbolAddress((void**)&pl2,  g_l2f);
    cudaGetSymbolAddress((void**)&pl,   g_lf);
    cudaGetSymbolAddress((void**)&pl1,  g_l1f);

    cudaFuncSetAttribute(edge_fused, cudaFuncAttributeMaxDynamicSharedMemorySize, EDGE_SMEM);
    cudaFuncSetAttribute(node_fused, cudaFuncAttributeMaxDynamicSharedMemorySize, NODE_SMEM);
    cudaFuncSetAttribute(gemm_plain, cudaFuncAttributeMaxDynamicSharedMemorySize, PLAIN_SMEM);

    const int* src = ei;
    const int* dst = ei + N_EDGES;

    embed_kernel<<<N_NODES, HID>>>(z, emb_w, emb_b, h);
    cmask_kernel<<<(N_EDGES + 255) / 256, 256>>>(elen, pC);
    pack_eattr<<<NTILES, 256>>>(eattr, peaf);
    {
        dim3 gw((6 * 8192 + 255) / 256, 5);
        pack_w<<<gw, 256>>>(nn_w1, nn_w2, lin2_w, lin_w, lin1_w, pw1, pw2, pl2, pl, pl1);
    }

    const int nodeTiles = (N_NODES + 127) / 128;   // 391
    const int aggN4 = N_NODES * HID / 4;

    gemm_plain<<<nodeTiles, NT, PLAIN_SMEM>>>(h, pl1, pxh, N_NODES);

    for (int i = 0; i < N_BLOCKS; i++) {
        zero_kernel<<<(aggN4 + 255) / 256, 256>>>((float4*)pagg, aggN4);
        edge_fused<<<NTILES, NT, EDGE_SMEM>>>(
            peaf, pw1 + i * 8192, nn_b1 + (size_t)i * HID,
            pw2 + i * 8192, nn_b2 + (size_t)i * HID,
            pC, src, dst, pxh, pagg);
        const uint32_t* lin1next = (i + 1 < N_BLOCKS) ? (pl1 + (i + 1) * 8192) : nullptr;
        node_fused<<<nodeTiles, NT, NODE_SMEM>>>(
            pagg, pl2 + i * 8192, lin2_b + (size_t)i * HID,
            pl + i * 8192, lin_b + (size_t)i * HID,
            h, lin1next, pxh);
    }
}

// round 14
// speedup vs baseline: 1.2382x; 1.0036x over previous
#include <cuda_runtime.h>
#include <cuda_fp16.h>
#include <cstdint>
#include <math.h>

#define N_NODES 50000
#define N_EDGES 800000
#define HID 128
#define EC 100
#define IN_DIM 5
#define N_BLOCKS 6
#define NT 512
#define NTILES 6250

// ---------------- scratch (device globals; no runtime allocation) ----------------
__device__ uint32_t g_xh[N_NODES * 64];        // x in half2 (12.8 MB)
__device__ float g_agg[N_NODES * HID];         // zero-init (BSS); every launch returns it to zero
__device__ float g_C[N_EDGES];
__device__ uint32_t g_eaf[(size_t)NTILES * 8192];   // eattr fragment-order fp16
__device__ uint32_t g_w1f[6 * 8192];
__device__ uint32_t g_w2f[6 * 8192];
__device__ uint32_t g_l2f[6 * 8192];
__device__ uint32_t g_lf [6 * 8192];
__device__ uint32_t g_l1f[6 * 8192];

__device__ __forceinline__ float sspf(float x) {
    float sp = fmaxf(x, 0.0f) + log1pf(expf(-fabsf(x)));
    return sp - 0.69314718055994531f;
}
__device__ __forceinline__ uint32_t h2(float lo, float hi) {
    uint32_t r;
    asm("cvt.rn.f16x2.f32 %0, %1, %2;" : "=r"(r) : "f"(hi), "f"(lo));
    return r;
}

// ---------------- fragment layout constants ----------------
#define KS_STR 132
#define AI_STR 264
#define AWORDS 2112
#define TI_STR 1056
#define TWORDS 8448
#define WS_STR 68                      // W tile row stride (words); 4g+t conflict-free
#define WWORDS (128 * WS_STR)          // 8704 words

#define EDGE_SMEM (WWORDS * 4)         // max(TWORDS, WWORDS) = WWORDS
#define NODE_SMEM ((TWORDS + 2 * AWORDS) * 4)
#define PLAIN_SMEM ((2 * AWORDS) * 4)

// ---------------- weight pre-pack ----------------
__global__ void __launch_bounds__(256) pack_w(
    const float* __restrict__ w1, const float* __restrict__ w2,
    const float* __restrict__ l2, const float* __restrict__ l,
    const float* __restrict__ l1,
    uint32_t* __restrict__ o1, uint32_t* __restrict__ o2,
    uint32_t* __restrict__ o3, uint32_t* __restrict__ o4,
    uint32_t* __restrict__ o5)
{
    const float* W; uint32_t* O; int K;
    switch (blockIdx.y) {
        case 0: W = w1; O = o1; K = EC;  break;
        case 1: W = w2; O = o2; K = 128; break;
        case 2: W = l2; O = o3; K = 128; break;
        case 3: W = l;  O = o4; K = 128; break;
        default: W = l1; O = o5; K = 128; break;
    }
    int idx = blockIdx.x * 256 + threadIdx.x;
    if (idx >= 6 * 8192) return;
    int blk = idx >> 13;
    int r = idx & 8191;
    int ch = r >> 11;
    int r2 = r & 2047;
    int pair = r2 >> 8;
    int ks = (r2 >> 7) & 1;
    int lane = (r2 >> 2) & 31;
    int w = r2 & 3;
    int g0 = lane >> 2, t = lane & 3;
    int jpar = w >> 1, wb = w & 1;
    int k = ch * 32 + ks * 16 + wb * 8 + t * 2;
    int n = pair * 16 + jpar * 8 + g0;
    const float* Wb = W + (size_t)blk * K * 128;
    float v0 = (k < K) ? Wb[(size_t)k * 128 + n] : 0.f;
    float v1 = (k + 1 < K) ? Wb[(size_t)(k + 1) * 128 + n] : 0.f;
    O[idx] = h2(v0, v1);
}

// ---------------- A loaders ----------------
__device__ __forceinline__ void loadA_g(float4* r, const float* __restrict__ A,
                                        int mBase, int k0, int M, int K, int tid) {
#pragma unroll
    for (int i = 0; i < 2; i++) {
        int q = tid + (i << 9);
        int row = q >> 3, kq = (q & 7) << 2;
        int gm = mBase + row, gk = k0 + kq;
        r[i] = make_float4(0.f, 0.f, 0.f, 0.f);
        if (gm < M && gk < K)
            r[i] = *reinterpret_cast<const float4*>(A + (size_t)gm * K + gk);
    }
}
// store zeros to the region just read (agg recycle)
__device__ __forceinline__ void zeroA_g(float* __restrict__ A, int mBase, int k0,
                                        int M, int K, int tid) {
#pragma unroll
    for (int i = 0; i < 2; i++) {
        int q = tid + (i << 9);
        int row = q >> 3, kq = (q & 7) << 2;
        int gm = mBase + row, gk = k0 + kq;
        if (gm < M && gk < K)
            *reinterpret_cast<float4*>(A + (size_t)gm * K + gk) =
                make_float4(0.f, 0.f, 0.f, 0.f);
    }
}
__device__ __forceinline__ void storeA_f(uint32_t* __restrict__ buf, const float4* r, int tid) {
#pragma unroll
    for (int i4 = 0; i4 < 2; i4++) {
        int q = tid + (i4 << 9);
        int row = q >> 3, kq = (q & 7) << 2;
        int iT = row >> 4, rl = row & 15;
        int g = rl & 7, hr = rl >> 3;
        int ks = kq >> 4, kl = kq & 15;
        int w = hr + ((kl & 8) ? 2 : 0);
        int t0 = (kl & 7) >> 1;
        uint32_t* p = buf + iT * AI_STR + ks * KS_STR + (g * 4 + t0) * 4 + w;
        p[0] = h2(r[i4].x, r[i4].y);
        p[4] = h2(r[i4].z, r[i4].w);
    }
}

// ---------------- fragment loads ----------------
__device__ __forceinline__ void loadB_frag(uint4* bv, const uint32_t* __restrict__ Bg,
                                           int ch, int wid, int lane) {
    const uint32_t* Bb = Bg + ch * 2048 + ((wid >> 2) * 2) * 256 + lane * 4;
#pragma unroll
    for (int ks = 0; ks < 2; ks++)
#pragma unroll
        for (int p = 0; p < 2; p++)
            bv[ks * 2 + p] = *reinterpret_cast<const uint4*>(Bb + p * 256 + ks * 128);
}
__device__ __forceinline__ void loadAe_frag(uint4* av, const uint32_t* __restrict__ Af, int ch) {
#pragma unroll
    for (int s = 0; s < 2; s++)
#pragma unroll
        for (int i = 0; i < 2; i++)
            av[s * 2 + i] = *reinterpret_cast<const uint4*>(Af + i * 1024 + (ch * 2 + s) * 128);
}

// ---------------- mma ----------------
__device__ __forceinline__ void mma8(float c[4][4], const uint4 av, const uint4* bv) {
#pragma unroll
    for (int j = 0; j < 4; j++) {
        uint32_t b0 = (j & 1) ? bv[j >> 1].z : bv[j >> 1].x;
        uint32_t b1 = (j & 1) ? bv[j >> 1].w : bv[j >> 1].y;
        asm volatile(
            "mma.sync.aligned.m16n8k16.row.col.f32.f16.f16.f32 "
            "{%0,%1,%2,%3}, {%4,%5,%6,%7}, {%8,%9}, {%0,%1,%2,%3};\n"
            : "+f"(c[j][0]), "+f"(c[j][1]), "+f"(c[j][2]), "+f"(c[j][3])
            : "r"(av.x), "r"(av.y), "r"(av.z), "r"(av.w), "r"(b0), "r"(b1));
    }
}
__device__ __forceinline__ void mma_bv(float c[2][4][4], const uint4* aC, const uint4* bv) {
#pragma unroll
    for (int ks = 0; ks < 2; ks++)
#pragma unroll
        for (int i = 0; i < 2; i++)
            mma8(c[i], aC[ks * 2 + i], &bv[ks * 2]);
}
template<int ISTR>
__device__ __forceinline__ void mma_s_bv(const uint32_t* __restrict__ As, const uint4* bv,
                                         float c[2][4][4], int wid, int lane)
{
    const uint32_t* Ab = As + ((wid & 3) * 2) * ISTR + lane * 4;
#pragma unroll
    for (int ks = 0; ks < 2; ks++) {
        uint4 av[2];
#pragma unroll
        for (int i = 0; i < 2; i++)
            av[i] = *reinterpret_cast<const uint4*>(Ab + i * ISTR + ks * KS_STR);
#pragma unroll
        for (int i = 0; i < 2; i++)
            mma8(c[i], av[i], &bv[ks * 2]);
    }
}

__device__ __forceinline__ void zero_c(float c[2][4][4]) {
#pragma unroll
    for (int i = 0; i < 2; i++)
#pragma unroll
        for (int j = 0; j < 4; j++)
#pragma unroll
            for (int v = 0; v < 4; v++) c[i][j][v] = 0.0f;
}

__device__ __forceinline__ void store_T_frag(uint32_t* __restrict__ Tt, const float c[2][4][4],
                                             const float* bn, int wid, int g, int t,
                                             int warpN, bool doSsp)
{
    const int iTb = (wid & 3) * 2;
    const int ksBase = warpN >> 4;
#pragma unroll
    for (int i = 0; i < 2; i++)
#pragma unroll
        for (int half = 0; half < 2; half++)
#pragma unroll
            for (int j = 0; j < 4; j++) {
                float v0 = c[i][j][half * 2 + 0] + bn[j * 2 + 0];
                float v1 = c[i][j][half * 2 + 1] + bn[j * 2 + 1];
                if (doSsp) { v0 = sspf(v0); v1 = sspf(v1); }
                int ks = ksBase + (j >> 1);
                int w = half + 2 * (j & 1);
                Tt[(iTb + i) * TI_STR + ks * KS_STR + (g * 4 + t) * 4 + w] = h2(v0, v1);
            }
}

// ---------------- eattr pre-pack (tile-staged, coalesced; proven R9/R11) ----------
__global__ void __launch_bounds__(256) pack_eattr(const float* __restrict__ ea,
                                                  uint32_t* __restrict__ out) {
    __shared__ uint32_t sf[8192];
    const int tile = blockIdx.x;
    const int tid = threadIdx.x;
    const int row = tid >> 1;
    const int kh = tid & 1;
    const float* er = ea + ((size_t)tile * 128 + row) * EC;
    const int iT = row >> 4, rl = row & 15;
    const int g = rl & 7, hr = rl >> 3;
#pragma unroll
    for (int q = 0; q < 4; q++) {
#pragma unroll
        for (int f4 = 0; f4 < 4; f4++) {
            int kq = kh * 64 + (q * 4 + f4) * 4;
            float4 v = make_float4(0.f, 0.f, 0.f, 0.f);
            if (kq < EC) {
                if (kq + 3 < EC)
                    v = *reinterpret_cast<const float4*>(er + kq);
                else {
                    v.x = er[kq];
                    if (kq + 1 < EC) v.y = er[kq + 1];
                    if (kq + 2 < EC) v.z = er[kq + 2];
                }
            }
            int ks = kq >> 4, kl = kq & 15;
            int w = hr + ((kl & 8) ? 2 : 0);
            int t0 = (kl & 7) >> 1;
            uint32_t* p = sf + iT * 1024 + ks * 128 + (g * 4 + t0) * 4 + w;
            p[0] = h2(v.x, v.y);
            p[4] = h2(v.z, v.w);
        }
    }
    __syncthreads();
    uint32_t* o = out + (size_t)tile * 8192;
#pragma unroll
    for (int i = 0; i < 8; i++)
        *reinterpret_cast<uint4*>(o + (tid + i * 256) * 4) =
            *reinterpret_cast<const uint4*>(sf + (tid + i * 256) * 4);
}

// ---------------- fused edge kernel ----------------
__global__ void __launch_bounds__(NT, 1) edge_fused(
    const uint32_t* __restrict__ eaf,
    const uint32_t* __restrict__ B1g, const float* __restrict__ b1,
    const uint32_t* __restrict__ B2g, const float* __restrict__ b2,
    const float* __restrict__ Cm, const int* __restrict__ src, const int* __restrict__ dst,
    const uint32_t* __restrict__ xh, float* __restrict__ agg)
{
    extern __shared__ uint32_t sm[];
    uint32_t* Tt = sm;            // T fragments (stage 1 out / stage 2 A)
    uint32_t* Wm = sm;            // reused after stage 2: W tile, [128 rows][WS_STR]

    const int tid = threadIdx.x;
    const int wid = tid >> 5, lane = tid & 31;
    const int g = lane >> 2, t = lane & 3;
    const int warpM = (wid & 3) * 32, warpN = (wid >> 2) * 32;
    const int mBase = blockIdx.x * 128;

    float c[2][4][4];
    zero_c(c);

    // stage 1: all-register, fully pipelined (A and B prefetch)
    const uint32_t* Af = eaf + (size_t)blockIdx.x * 8192 + ((wid & 3) * 2) * 1024 + lane * 4;
    uint4 aC[4], bv[4], aN[4], bN[4];
    loadAe_frag(aC, Af, 0);
    loadB_frag(bv, B1g, 0, wid, lane);
#pragma unroll
    for (int ch = 0; ch < 4; ch++) {
        if (ch < 3) {
            loadAe_frag(aN, Af, ch + 1);
            loadB_frag(bN, B1g, ch + 1, wid, lane);
        }
        mma_bv(c, aC, bv);
        if (ch < 3) {
#pragma unroll
            for (int q = 0; q < 4; q++) { aC[q] = aN[q]; bv[q] = bN[q]; }
        }
    }

    float bn1[8];
#pragma unroll
    for (int j = 0; j < 4; j++) {
        bn1[j * 2 + 0] = __ldg(b1 + warpN + j * 8 + t * 2 + 0);
        bn1[j * 2 + 1] = __ldg(b1 + warpN + j * 8 + t * 2 + 1);
    }
    store_T_frag(Tt, c, bn1, wid, g, t, warpN, true);
    zero_c(c);
    loadB_frag(bv, B2g, 0, wid, lane);
    __syncthreads();   // T visible to all warps

    // stage 2: T (smem) @ B2, B pipelined
#pragma unroll
    for (int ch = 0; ch < 4; ch++) {
        if (ch < 3) loadB_frag(bN, B2g, ch + 1, wid, lane);
        mma_s_bv<TI_STR>(Tt + ch * 2 * KS_STR, bv, c, wid, lane);
        if (ch < 3) {
#pragma unroll
            for (int q = 0; q < 4; q++) bv[q] = bN[q];
        }
    }
    __syncthreads();   // all warps done reading Tt; safe to overwrite with W

    // stage-2 epilogue: W(+bias) -> smem as half2, row stride WS_STR
    float bn2[8];
#pragma unroll
    for (int j = 0; j < 4; j++) {
        bn2[j * 2 + 0] = __ldg(b2 + warpN + j * 8 + t * 2 + 0);
        bn2[j * 2 + 1] = __ldg(b2 + warpN + j * 8 + t * 2 + 1);
    }
#pragma unroll
    for (int i = 0; i < 2; i++)
#pragma unroll
        for (int half = 0; half < 2; half++) {
            const int row = warpM + i * 16 + g + half * 8;
#pragma unroll
            for (int j = 0; j < 4; j++) {
                float v0 = c[i][j][half * 2 + 0] + bn2[j * 2 + 0];
                float v1 = c[i][j][half * 2 + 1] + bn2[j * 2 + 1];
                Wm[row * WS_STR + (warpN >> 1) + j * 4 + t] = h2(v0, v1);
            }
        }
    __syncthreads();

    // warp-per-edge scatter: 8 edges per warp, fully coalesced gather + red.v4
    for (int it = 0; it < 8; it++) {
        const int e = mBase + wid * 8 + it;
        const float cmv = __ldg(Cm + e);
        if (cmv != 0.0f) {
            const int s = __ldg(src + e);
            const int d = __ldg(dst + e);
            uint2 Wp = *reinterpret_cast<const uint2*>(Wm + (wid * 8 + it) * WS_STR + lane * 2);
            uint2 xp = __ldg(reinterpret_cast<const uint2*>(xh + (size_t)s * 64 + lane * 2));
            float2 w01 = __half22float2(*reinterpret_cast<const __half2*>(&Wp.x));
            float2 w23 = __half22float2(*reinterpret_cast<const __half2*>(&Wp.y));
            float2 x01 = __half22float2(*reinterpret_cast<const __half2*>(&xp.x));
            float2 x23 = __half22float2(*reinterpret_cast<const __half2*>(&xp.y));
            float m0 = x01.x * w01.x, m1 = x01.y * w01.y;
            float m2 = x23.x * w23.x, m3 = x23.y * w23.y;
            asm volatile("red.global.add.v4.f32 [%0], {%1, %2, %3, %4};"
                         :: "l"(agg + (size_t)d * 128 + lane * 4),
                            "f"(m0), "f"(m1), "f"(m2), "f"(m3) : "memory");
        }
    }
}

// ---------------- fused node kernel ----------------
__global__ void __launch_bounds__(NT, 1) node_fused(
    const float* __restrict__ agg, float* __restrict__ aggW,
    const uint32_t* __restrict__ B1g, const float* __restrict__ b1,
    const uint32_t* __restrict__ B2g, const float* __restrict__ b2,
    float* __restrict__ h, const uint32_t* __restrict__ B3g, uint32_t* __restrict__ xOut)
{
    extern __shared__ uint32_t sm[];
    uint32_t* Tt  = sm;
    uint32_t* As0 = sm + TWORDS;
    uint32_t* As1 = As0 + AWORDS;

    const int tid = threadIdx.x;
    const int wid = tid >> 5, lane = tid & 31;
    const int g = lane >> 2, t = lane & 3;
    const int warpM = (wid & 3) * 32, warpN = (wid >> 2) * 32;
    const int mBase = blockIdx.x * 128;

    float c[2][4][4];
    zero_c(c);
    float4 aR[2];
    uint4 bv[4], bN[4];

    // stage 1: agg (smem-staged A, double-buffered) @ B1; zero agg behind the read
    loadA_g(aR, agg, mBase, 0, N_NODES, 128, tid);
    zeroA_g(aggW, mBase, 0, N_NODES, 128, tid);
    loadB_frag(bv, B1g, 0, wid, lane);
    storeA_f(As0, aR, tid);
    __syncthreads();
#pragma unroll
    for (int ch = 0; ch < 4; ch++) {
        if (ch < 3) {
            loadA_g(aR, agg, mBase, (ch + 1) * 32, N_NODES, 128, tid);
            zeroA_g(aggW, mBase, (ch + 1) * 32, N_NODES, 128, tid);
            loadB_frag(bN, B1g, ch + 1, wid, lane);
        }
        mma_s_bv<AI_STR>((ch & 1) ? As1 : As0, bv, c, wid, lane);
        if (ch < 3) {
            storeA_f(((ch + 1) & 1) ? As1 : As0, aR, tid);
#pragma unroll
            for (int q = 0; q < 4; q++) bv[q] = bN[q];
        }
        __syncthreads();
    }

    float bn1[8];
#pragma unroll
    for (int j = 0; j < 4; j++) {
        bn1[j * 2 + 0] = __ldg(b1 + warpN + j * 8 + t * 2 + 0);
        bn1[j * 2 + 1] = __ldg(b1 + warpN + j * 8 + t * 2 + 1);
    }
    store_T_frag(Tt, c, bn1, wid, g, t, warpN, true);
    zero_c(c);
    loadB_frag(bv, B2g, 0, wid, lane);
    __syncthreads();

    // stage 2: T @ B2 (B pipelined)
#pragma unroll
    for (int ch = 0; ch < 4; ch++) {
        if (ch < 3) loadB_frag(bN, B2g, ch + 1, wid, lane);
        mma_s_bv<TI_STR>(Tt + ch * 2 * KS_STR, bv, c, wid, lane);
        if (ch < 3) {
#pragma unroll
            for (int q = 0; q < 4; q++) bv[q] = bN[q];
        }
    }
    __syncthreads();   // all warps done reading Tt before epilogue overwrites it

    // stage-2 epilogue: h += residual; keep hnew resident in T-frag
    float bn2[8];
#pragma unroll
    for (int j = 0; j < 4; j++) {
        bn2[j * 2 + 0] = __ldg(b2 + warpN + j * 8 + t * 2 + 0);
        bn2[j * 2 + 1] = __ldg(b2 + warpN + j * 8 + t * 2 + 1);
    }
    const int iTb = (wid & 3) * 2;
    const int ksBase = warpN >> 4;
#pragma unroll
    for (int i = 0; i < 2; i++)
#pragma unroll
        for (int half = 0; half < 2; half++) {
            const int gm = mBase + warpM + i * 16 + g + half * 8;
            const bool ok = gm < N_NODES;
            float* hrow = h + (size_t)gm * 128;
#pragma unroll
            for (int j = 0; j < 4; j++) {
                const int col = warpN + j * 8 + t * 2;
                float v0 = c[i][j][half * 2 + 0] + bn2[j * 2 + 0];
                float v1 = c[i][j][half * 2 + 1] + bn2[j * 2 + 1];
                if (ok) {
                    float2 hv = *reinterpret_cast<const float2*>(hrow + col);
                    v0 += hv.x; v1 += hv.y;
                    *reinterpret_cast<float2*>(hrow + col) = make_float2(v0, v1);
                }
                int ks = ksBase + (j >> 1);
                int w = half + 2 * (j & 1);
                Tt[(iTb + i) * TI_STR + ks * KS_STR + (g * 4 + t) * 4 + w] = h2(v0, v1);
            }
        }

    // stage 3: xOut(half2) = hnew @ lin1next (B pipelined)
    if (B3g != nullptr) {
        zero_c(c);
        loadB_frag(bv, B3g, 0, wid, lane);
        __syncthreads();   // hnew T-frag complete
#pragma unroll
        for (int ch = 0; ch < 4; ch++) {
            if (ch < 3) loadB_frag(bN, B3g, ch + 1, wid, lane);
            mma_s_bv<TI_STR>(Tt + ch * 2 * KS_STR, bv, c, wid, lane);
            if (ch < 3) {
#pragma unroll
                for (int q = 0; q < 4; q++) bv[q] = bN[q];
            }
        }
#pragma unroll
        for (int i = 0; i < 2; i++)
#pragma unroll
            for (int half = 0; half < 2; half++) {
                const int gm = mBase + warpM + i * 16 + g + half * 8;
                if (gm < N_NODES) {
                    uint32_t* orow = xOut + (size_t)gm * 64;
#pragma unroll
                    for (int j = 0; j < 4; j++) {
                        const int col = warpN + j * 8 + t * 2;
                        orow[col >> 1] = h2(c[i][j][half * 2 + 0], c[i][j][half * 2 + 1]);
                    }
                }
            }
    }
}

// ---------------- plain GEMM (initial x = h @ lin1_0, half2 out) ------------------
__global__ void __launch_bounds__(NT, 1) gemm_plain(
    const float* __restrict__ A, const uint32_t* __restrict__ Bg,
    uint32_t* __restrict__ out, int M)
{
    extern __shared__ uint32_t sm[];
    uint32_t* As0 = sm;
    uint32_t* As1 = As0 + AWORDS;

    const int tid = threadIdx.x;
    const int wid = tid >> 5, lane = tid & 31;
    const int g = lane >> 2, t = lane & 3;
    const int warpM = (wid & 3) * 32, warpN = (wid >> 2) * 32;
    const int mBase = blockIdx.x * 128;

    float c[2][4][4];
    zero_c(c);
    float4 aR[2];
    uint4 bv[4], bN[4];
    loadA_g(aR, A, mBase, 0, M, 128, tid);
    loadB_frag(bv, Bg, 0, wid, lane);
    storeA_f(As0, aR, tid);
    __syncthreads();
#pragma unroll
    for (int ch = 0; ch < 4; ch++) {
        if (ch < 3) {
            loadA_g(aR, A, mBase, (ch + 1) * 32, M, 128, tid);
            loadB_frag(bN, Bg, ch + 1, wid, lane);
        }
        mma_s_bv<AI_STR>((ch & 1) ? As1 : As0, bv, c, wid, lane);
        if (ch < 3) {
            storeA_f(((ch + 1) & 1) ? As1 : As0, aR, tid);
#pragma unroll
            for (int q = 0; q < 4; q++) bv[q] = bN[q];
        }
        __syncthreads();
    }
#pragma unroll
    for (int i = 0; i < 2; i++)
#pragma unroll
        for (int half = 0; half < 2; half++) {
            const int gm = mBase + warpM + i * 16 + g + half * 8;
            if (gm < M) {
                uint32_t* orow = out + (size_t)gm * 64;
#pragma unroll
                for (int j = 0; j < 4; j++) {
                    const int col = warpN + j * 8 + t * 2;
                    orow[col >> 1] = h2(c[i][j][half * 2 + 0], c[i][j][half * 2 + 1]);
                }
            }
        }
}

// ---------------- small kernels ----------------
__global__ void embed_kernel(const float* __restrict__ z, const float* __restrict__ w,
                             const float* __restrict__ b, float* __restrict__ h) {
    int n = blockIdx.x, j = threadIdx.x;
    const float* zr = z + (size_t)n * (IN_DIM + HID);
    float acc = b[j] + zr[IN_DIM + j];
#pragma unroll
    for (int k = 0; k < IN_DIM; k++) acc = fmaf(zr[k], w[k * HID + j], acc);
    h[(size_t)n * HID + j] = acc;
}

__global__ void cmask_kernel(const float* __restrict__ len, float* __restrict__ C) {
    int e = blockIdx.x * 256 + threadIdx.x;
    if (e < N_EDGES) {
        float l = len[e];
        C[e] = (l <= 10.0f && l >= 0.0f) ? 1.0f : 0.0f;
    }
}

// ---------------- host launch ----------------
extern "C" void kernel_launch(void* const* d_in, const int* in_sizes, int n_in,
                              void* d_out, int out_size) {
    const float* z      = (const float*)d_in[0];
    const int*   ei     = (const int*)  d_in[1];
    const float* elen   = (const float*)d_in[2];
    const float* eattr  = (const float*)d_in[3];
    const float* emb_w  = (const float*)d_in[4];
    const float* emb_b  = (const float*)d_in[5];
    const float* lin1_w = (const float*)d_in[6];
    const float* nn_w1  = (const float*)d_in[7];
    const float* nn_b1  = (const float*)d_in[8];
    const float* nn_w2  = (const float*)d_in[9];
    const float* nn_b2  = (const float*)d_in[10];
    const float* lin2_w = (const float*)d_in[11];
    const float* lin2_b = (const float*)d_in[12];
    const float* lin_w  = (const float*)d_in[13];
    const float* lin_b  = (const float*)d_in[14];
    float* h = (float*)d_out;

    float *pagg, *pC;
    uint32_t *pxh, *peaf, *pw1, *pw2, *pl2, *pl, *pl1;
    cudaGetSymbolAddress((void**)&pxh,  g_xh);
    cudaGetSymbolAddress((void**)&pagg, g_agg);
    cudaGetSymbolAddress((void**)&pC,   g_C);
    cudaGetSymbolAddress((void**)&peaf, g_eaf);
    cudaGetSymbolAddress((void**)&pw1,  g_w1f);
    cudaGetSymbolAddress((void**)&pw2,  g_w2f);
    cudaGetSymbolAddress((void**)&pl2,  g_l2f);
    cudaGetSymbolAddress((void**)&pl,   g_lf);
    cudaGetSymbolAddress((void**)&pl1,  g_l1f);

    cudaFuncSetAttribute(edge_fused, cudaFuncAttributeMaxDynamicSharedMemorySize, EDGE_SMEM);
    cudaFuncSetAttribute(node_fused, cudaFuncAttributeMaxDynamicSharedMemorySize, NODE_SMEM);
    cudaFuncSetAttribute(gemm_plain, cudaFuncAttributeMaxDynamicSharedMemorySize, PLAIN_SMEM);

    const int* src = ei;
    const int* dst = ei + N_EDGES;

    embed_kernel<<<N_NODES, HID>>>(z, emb_w, emb_b, h);
    cmask_kernel<<<(N_EDGES + 255) / 256, 256>>>(elen, pC);
    pack_eattr<<<NTILES, 256>>>(eattr, peaf);
    {
        dim3 gw((6 * 8192 + 255) / 256, 5);
        pack_w<<<gw, 256>>>(nn_w1, nn_w2, lin2_w, lin_w, lin1_w, pw1, pw2, pl2, pl, pl1);
    }

    const int nodeTiles = (N_NODES + 127) / 128;   // 391

    gemm_plain<<<nodeTiles, NT, PLAIN_SMEM>>>(h, pl1, pxh, N_NODES);

    // g_agg starts zero (BSS) and every node_fused re-zeroes it after reading,
    // so each graph replay sees a zeroed agg without explicit zero kernels.
    for (int i = 0; i < N_BLOCKS; i++) {
        edge_fused<<<NTILES, NT, EDGE_SMEM>>>(
            peaf, pw1 + i * 8192, nn_b1 + (size_t)i * HID,
            pw2 + i * 8192, nn_b2 + (size_t)i * HID,
            pC, src, dst, pxh, pagg);
        const uint32_t* lin1next = (i + 1 < N_BLOCKS) ? (pl1 + (i + 1) * 8192) : nullptr;
        node_fused<<<nodeTiles, NT, NODE_SMEM>>>(
            pagg, pagg, pl2 + i * 8192, lin2_b + (size_t)i * HID,
            pl + i * 8192, lin_b + (size_t)i * HID,
            h, lin1next, pxh);
    }
}

// round 15
// speedup vs baseline: 1.4124x; 1.1407x over previous
#include <cuda_runtime.h>
#include <cuda_fp16.h>
#include <cstdint>
#include <math.h>

#define N_NODES 50000
#define N_EDGES 800000
#define HID 128
#define EC 100
#define IN_DIM 5
#define N_BLOCKS 6
#define NT 512
#define NTE 256
#define NTILES 6250
#define ETILES 12500

// ---------------- scratch (device globals; no runtime allocation) ----------------
__device__ uint32_t g_xh[N_NODES * 64];        // x in half2 (12.8 MB)
__device__ float g_agg[N_NODES * HID];         // zero-init (BSS); launches return it to zero
__device__ float g_C[N_EDGES];
__device__ uint32_t g_eaf[(size_t)NTILES * 8192];   // eattr fragment-order fp16
__device__ uint32_t g_w1f[6 * 8192];
__device__ uint32_t g_w2f[6 * 8192];
__device__ uint32_t g_l2f[6 * 8192];
__device__ uint32_t g_lf [6 * 8192];
__device__ uint32_t g_l1f[6 * 8192];

__device__ __forceinline__ float sspf(float x) {
    float sp = fmaxf(x, 0.0f) + log1pf(expf(-fabsf(x)));
    return sp - 0.69314718055994531f;
}
__device__ __forceinline__ uint32_t h2(float lo, float hi) {
    uint32_t r;
    asm("cvt.rn.f16x2.f32 %0, %1, %2;" : "=r"(r) : "f"(hi), "f"(lo));
    return r;
}

// ---------------- fragment layout constants ----------------
#define KS_STR 132
#define AI_STR 264
#define AWORDS 2112
#define TI_STR 1056
#define TWORDS 8448            // node kernel: 8 i-tiles
#define TWORDS_E 4224          // edge kernel: 4 i-tiles (64 rows)
#define WS_STR 68
#define WWORDS_E (64 * WS_STR) // 4352 words

#define EDGE_SMEM (WWORDS_E * 4)               // max(TWORDS_E, WWORDS_E)*4 = 17408
#define NODE_SMEM ((TWORDS + 2 * AWORDS) * 4)
#define PLAIN_SMEM ((2 * AWORDS) * 4)

// ---------------- weight pre-pack ----------------
__global__ void __launch_bounds__(256) pack_w(
    const float* __restrict__ w1, const float* __restrict__ w2,
    const float* __restrict__ l2, const float* __restrict__ l,
    const float* __restrict__ l1,
    uint32_t* __restrict__ o1, uint32_t* __restrict__ o2,
    uint32_t* __restrict__ o3, uint32_t* __restrict__ o4,
    uint32_t* __restrict__ o5)
{
    const float* W; uint32_t* O; int K;
    switch (blockIdx.y) {
        case 0: W = w1; O = o1; K = EC;  break;
        case 1: W = w2; O = o2; K = 128; break;
        case 2: W = l2; O = o3; K = 128; break;
        case 3: W = l;  O = o4; K = 128; break;
        default: W = l1; O = o5; K = 128; break;
    }
    int idx = blockIdx.x * 256 + threadIdx.x;
    if (idx >= 6 * 8192) return;
    int blk = idx >> 13;
    int r = idx & 8191;
    int ch = r >> 11;
    int r2 = r & 2047;
    int pair = r2 >> 8;
    int ks = (r2 >> 7) & 1;
    int lane = (r2 >> 2) & 31;
    int w = r2 & 3;
    int g0 = lane >> 2, t = lane & 3;
    int jpar = w >> 1, wb = w & 1;
    int k = ch * 32 + ks * 16 + wb * 8 + t * 2;
    int n = pair * 16 + jpar * 8 + g0;
    const float* Wb = W + (size_t)blk * K * 128;
    float v0 = (k < K) ? Wb[(size_t)k * 128 + n] : 0.f;
    float v1 = (k + 1 < K) ? Wb[(size_t)(k + 1) * 128 + n] : 0.f;
    O[idx] = h2(v0, v1);
}

// ---------------- A loaders (node path, 512 threads) ----------------
__device__ __forceinline__ void loadA_g(float4* r, const float* __restrict__ A,
                                        int mBase, int k0, int M, int K, int tid) {
#pragma unroll
    for (int i = 0; i < 2; i++) {
        int q = tid + (i << 9);
        int row = q >> 3, kq = (q & 7) << 2;
        int gm = mBase + row, gk = k0 + kq;
        r[i] = make_float4(0.f, 0.f, 0.f, 0.f);
        if (gm < M && gk < K)
            r[i] = *reinterpret_cast<const float4*>(A + (size_t)gm * K + gk);
    }
}
__device__ __forceinline__ void zeroA_g(float* __restrict__ A, int mBase, int k0,
                                        int M, int K, int tid) {
#pragma unroll
    for (int i = 0; i < 2; i++) {
        int q = tid + (i << 9);
        int row = q >> 3, kq = (q & 7) << 2;
        int gm = mBase + row, gk = k0 + kq;
        if (gm < M && gk < K)
            *reinterpret_cast<float4*>(A + (size_t)gm * K + gk) =
                make_float4(0.f, 0.f, 0.f, 0.f);
    }
}
__device__ __forceinline__ void storeA_f(uint32_t* __restrict__ buf, const float4* r, int tid) {
#pragma unroll
    for (int i4 = 0; i4 < 2; i4++) {
        int q = tid + (i4 << 9);
        int row = q >> 3, kq = (q & 7) << 2;
        int iT = row >> 4, rl = row & 15;
        int g = rl & 7, hr = rl >> 3;
        int ks = kq >> 4, kl = kq & 15;
        int w = hr + ((kl & 8) ? 2 : 0);
        int t0 = (kl & 7) >> 1;
        uint32_t* p = buf + iT * AI_STR + ks * KS_STR + (g * 4 + t0) * 4 + w;
        p[0] = h2(r[i4].x, r[i4].y);
        p[4] = h2(r[i4].z, r[i4].w);
    }
}

// ---------------- fragment loads ----------------
// widn = warp's N index (warpN/32)
__device__ __forceinline__ void loadB_frag(uint4* bv, const uint32_t* __restrict__ Bg,
                                           int ch, int widn, int lane) {
    const uint32_t* Bb = Bg + ch * 2048 + (widn * 2) * 256 + lane * 4;
#pragma unroll
    for (int ks = 0; ks < 2; ks++)
#pragma unroll
        for (int p = 0; p < 2; p++)
            bv[ks * 2 + p] = *reinterpret_cast<const uint4*>(Bb + p * 256 + ks * 128);
}
__device__ __forceinline__ void loadAe_frag(uint4* av, const uint32_t* __restrict__ Af, int ch) {
#pragma unroll
    for (int s = 0; s < 2; s++)
#pragma unroll
        for (int i = 0; i < 2; i++)
            av[s * 2 + i] = *reinterpret_cast<const uint4*>(Af + i * 1024 + (ch * 2 + s) * 128);
}

// ---------------- mma ----------------
__device__ __forceinline__ void mma8(float c[4][4], const uint4 av, const uint4* bv) {
#pragma unroll
    for (int j = 0; j < 4; j++) {
        uint32_t b0 = (j & 1) ? bv[j >> 1].z : bv[j >> 1].x;
        uint32_t b1 = (j & 1) ? bv[j >> 1].w : bv[j >> 1].y;
        asm volatile(
            "mma.sync.aligned.m16n8k16.row.col.f32.f16.f16.f32 "
            "{%0,%1,%2,%3}, {%4,%5,%6,%7}, {%8,%9}, {%0,%1,%2,%3};\n"
            : "+f"(c[j][0]), "+f"(c[j][1]), "+f"(c[j][2]), "+f"(c[j][3])
            : "r"(av.x), "r"(av.y), "r"(av.z), "r"(av.w), "r"(b0), "r"(b1));
    }
}
__device__ __forceinline__ void mma_bv(float c[2][4][4], const uint4* aC, const uint4* bv) {
#pragma unroll
    for (int ks = 0; ks < 2; ks++)
#pragma unroll
        for (int i = 0; i < 2; i++)
            mma8(c[i], aC[ks * 2 + i], &bv[ks * 2]);
}
// A from smem: Ab = base of this warp's first i-tile
__device__ __forceinline__ void mma_s_bv(const uint32_t* __restrict__ Ab, int istr,
                                         const uint4* bv, float c[2][4][4])
{
#pragma unroll
    for (int ks = 0; ks < 2; ks++) {
        uint4 av[2];
#pragma unroll
        for (int i = 0; i < 2; i++)
            av[i] = *reinterpret_cast<const uint4*>(Ab + i * istr + ks * KS_STR);
#pragma unroll
        for (int i = 0; i < 2; i++)
            mma8(c[i], av[i], &bv[ks * 2]);
    }
}

__device__ __forceinline__ void zero_c(float c[2][4][4]) {
#pragma unroll
    for (int i = 0; i < 2; i++)
#pragma unroll
        for (int j = 0; j < 4; j++)
#pragma unroll
            for (int v = 0; v < 4; v++) c[i][j][v] = 0.0f;
}

// store epilogue values into T fragment layout; iTb = warp's first i-tile
__device__ __forceinline__ void store_T_frag(uint32_t* __restrict__ Tt, const float c[2][4][4],
                                             const float* bn, int iTb, int g, int t,
                                             int warpN, bool doSsp)
{
    const int ksBase = warpN >> 4;
#pragma unroll
    for (int i = 0; i < 2; i++)
#pragma unroll
        for (int half = 0; half < 2; half++)
#pragma unroll
            for (int j = 0; j < 4; j++) {
                float v0 = c[i][j][half * 2 + 0] + bn[j * 2 + 0];
                float v1 = c[i][j][half * 2 + 1] + bn[j * 2 + 1];
                if (doSsp) { v0 = sspf(v0); v1 = sspf(v1); }
                int ks = ksBase + (j >> 1);
                int w = half + 2 * (j & 1);
                Tt[(iTb + i) * TI_STR + ks * KS_STR + (g * 4 + t) * 4 + w] = h2(v0, v1);
            }
}

// ---------------- eattr pre-pack (tile-staged, coalesced; proven R9/R11) ----------
__global__ void __launch_bounds__(256) pack_eattr(const float* __restrict__ ea,
                                                  uint32_t* __restrict__ out) {
    __shared__ uint32_t sf[8192];
    const int tile = blockIdx.x;
    const int tid = threadIdx.x;
    const int row = tid >> 1;
    const int kh = tid & 1;
    const float* er = ea + ((size_t)tile * 128 + row) * EC;
    const int iT = row >> 4, rl = row & 15;
    const int g = rl & 7, hr = rl >> 3;
#pragma unroll
    for (int q = 0; q < 4; q++) {
#pragma unroll
        for (int f4 = 0; f4 < 4; f4++) {
            int kq = kh * 64 + (q * 4 + f4) * 4;
            float4 v = make_float4(0.f, 0.f, 0.f, 0.f);
            if (kq < EC) {
                if (kq + 3 < EC)
                    v = *reinterpret_cast<const float4*>(er + kq);
                else {
                    v.x = er[kq];
                    if (kq + 1 < EC) v.y = er[kq + 1];
                    if (kq + 2 < EC) v.z = er[kq + 2];
                }
            }
            int ks = kq >> 4, kl = kq & 15;
            int w = hr + ((kl & 8) ? 2 : 0);
            int t0 = (kl & 7) >> 1;
            uint32_t* p = sf + iT * 1024 + ks * 128 + (g * 4 + t0) * 4 + w;
            p[0] = h2(v.x, v.y);
            p[4] = h2(v.z, v.w);
        }
    }
    __syncthreads();
    uint32_t* o = out + (size_t)tile * 8192;
#pragma unroll
    for (int i = 0; i < 8; i++)
        *reinterpret_cast<uint4*>(o + (tid + i * 256) * 4) =
            *reinterpret_cast<const uint4*>(sf + (tid + i * 256) * 4);
}

// ---------------- fused edge kernel: 64-edge tiles, 256 threads, 2 CTAs/SM --------
__global__ void __launch_bounds__(NTE, 2) edge_fused(
    const uint32_t* __restrict__ eaf,
    const uint32_t* __restrict__ B1g, const float* __restrict__ b1,
    const uint32_t* __restrict__ B2g, const float* __restrict__ b2,
    const float* __restrict__ Cm, const int* __restrict__ src, const int* __restrict__ dst,
    const uint32_t* __restrict__ xh, float* __restrict__ agg)
{
    extern __shared__ uint32_t sm[];
    uint32_t* Tt = sm;
    uint32_t* Wm = sm;

    const int tid = threadIdx.x;
    const int wid = tid >> 5, lane = tid & 31;
    const int g = lane >> 2, t = lane & 3;
    const int widm = wid & 1, widn = wid >> 1;     // 2(M) x 4(N) warps
    const int warpM = widm * 32, warpN = widn * 32;
    const int mBase = blockIdx.x * 64;
    const int iTb = widm * 2;

    float c[2][4][4];
    zero_c(c);

    // stage 1: A frags from gmem (this CTA's half of a 128-edge pack tile)
    const uint32_t* Af = eaf + (size_t)(blockIdx.x >> 1) * 8192
                       + ((blockIdx.x & 1) * 4 + widm * 2) * 1024 + lane * 4;
    uint4 aC[4], bv[4], aN[4], bN[4];
    loadAe_frag(aC, Af, 0);
    loadB_frag(bv, B1g, 0, widn, lane);
#pragma unroll
    for (int ch = 0; ch < 4; ch++) {
        if (ch < 3) {
            loadAe_frag(aN, Af, ch + 1);
            loadB_frag(bN, B1g, ch + 1, widn, lane);
        }
        mma_bv(c, aC, bv);
        if (ch < 3) {
#pragma unroll
            for (int q = 0; q < 4; q++) { aC[q] = aN[q]; bv[q] = bN[q]; }
        }
    }

    float bn1[8];
#pragma unroll
    for (int j = 0; j < 4; j++) {
        bn1[j * 2 + 0] = __ldg(b1 + warpN + j * 8 + t * 2 + 0);
        bn1[j * 2 + 1] = __ldg(b1 + warpN + j * 8 + t * 2 + 1);
    }
    store_T_frag(Tt, c, bn1, iTb, g, t, warpN, true);
    zero_c(c);
    loadB_frag(bv, B2g, 0, widn, lane);
    __syncthreads();   // T visible to all warps

    // stage 2: T (smem) @ B2, B pipelined
    const uint32_t* Ab = Tt + iTb * TI_STR + lane * 4;
#pragma unroll
    for (int ch = 0; ch < 4; ch++) {
        if (ch < 3) loadB_frag(bN, B2g, ch + 1, widn, lane);
        mma_s_bv(Ab + ch * 2 * KS_STR, TI_STR, bv, c);
        if (ch < 3) {
#pragma unroll
            for (int q = 0; q < 4; q++) bv[q] = bN[q];
        }
    }
    __syncthreads();   // done reading Tt; safe to overwrite with W

    // epilogue: W(+bias) -> smem half2
    float bn2[8];
#pragma unroll
    for (int j = 0; j < 4; j++) {
        bn2[j * 2 + 0] = __ldg(b2 + warpN + j * 8 + t * 2 + 0);
        bn2[j * 2 + 1] = __ldg(b2 + warpN + j * 8 + t * 2 + 1);
    }
#pragma unroll
    for (int i = 0; i < 2; i++)
#pragma unroll
        for (int half = 0; half < 2; half++) {
            const int row = warpM + i * 16 + g + half * 8;
#pragma unroll
            for (int j = 0; j < 4; j++) {
                float v0 = c[i][j][half * 2 + 0] + bn2[j * 2 + 0];
                float v1 = c[i][j][half * 2 + 1] + bn2[j * 2 + 1];
                Wm[row * WS_STR + (warpN >> 1) + j * 4 + t] = h2(v0, v1);
            }
        }
    __syncthreads();

    // warp-per-edge scatter: 8 edges per warp, coalesced gather + red.v4
#pragma unroll
    for (int it = 0; it < 8; it++) {
        const int e = mBase + wid * 8 + it;
        const float cmv = __ldg(Cm + e);
        if (cmv != 0.0f) {
            const int s = __ldg(src + e);
            const int d = __ldg(dst + e);
            uint2 Wp = *reinterpret_cast<const uint2*>(Wm + (wid * 8 + it) * WS_STR + lane * 2);
            uint2 xp = __ldg(reinterpret_cast<const uint2*>(xh + (size_t)s * 64 + lane * 2));
            float2 w01 = __half22float2(*reinterpret_cast<const __half2*>(&Wp.x));
            float2 w23 = __half22float2(*reinterpret_cast<const __half2*>(&Wp.y));
            float2 x01 = __half22float2(*reinterpret_cast<const __half2*>(&xp.x));
            float2 x23 = __half22float2(*reinterpret_cast<const __half2*>(&xp.y));
            float m0 = x01.x * w01.x, m1 = x01.y * w01.y;
            float m2 = x23.x * w23.x, m3 = x23.y * w23.y;
            asm volatile("red.global.add.v4.f32 [%0], {%1, %2, %3, %4};"
                         :: "l"(agg + (size_t)d * 128 + lane * 4),
                            "f"(m0), "f"(m1), "f"(m2), "f"(m3) : "memory");
        }
    }
}

// ---------------- fused node kernel (512 threads, unchanged structure) ------------
__global__ void __launch_bounds__(NT, 1) node_fused(
    const float* __restrict__ agg, float* __restrict__ aggW,
    const uint32_t* __restrict__ B1g, const float* __restrict__ b1,
    const uint32_t* __restrict__ B2g, const float* __restrict__ b2,
    float* __restrict__ h, const uint32_t* __restrict__ B3g, uint32_t* __restrict__ xOut)
{
    extern __shared__ uint32_t sm[];
    uint32_t* Tt  = sm;
    uint32_t* As0 = sm + TWORDS;
    uint32_t* As1 = As0 + AWORDS;

    const int tid = threadIdx.x;
    const int wid = tid >> 5, lane = tid & 31;
    const int g = lane >> 2, t = lane & 3;
    const int widm = wid & 3, widn = wid >> 2;
    const int warpM = widm * 32, warpN = widn * 32;
    const int mBase = blockIdx.x * 128;
    const int iTb = widm * 2;

    float c[2][4][4];
    zero_c(c);
    float4 aR[2];
    uint4 bv[4], bN[4];

    // stage 1: agg (smem-staged, double-buffered) @ B1; zero agg behind the read
    loadA_g(aR, agg, mBase, 0, N_NODES, 128, tid);
    zeroA_g(aggW, mBase, 0, N_NODES, 128, tid);
    loadB_frag(bv, B1g, 0, widn, lane);
    storeA_f(As0, aR, tid);
    __syncthreads();
#pragma unroll
    for (int ch = 0; ch < 4; ch++) {
        if (ch < 3) {
            loadA_g(aR, agg, mBase, (ch + 1) * 32, N_NODES, 128, tid);
            zeroA_g(aggW, mBase, (ch + 1) * 32, N_NODES, 128, tid);
            loadB_frag(bN, B1g, ch + 1, widn, lane);
        }
        mma_s_bv(((ch & 1) ? As1 : As0) + iTb * AI_STR + lane * 4, AI_STR, bv, c);
        if (ch < 3) {
            storeA_f(((ch + 1) & 1) ? As1 : As0, aR, tid);
#pragma unroll
            for (int q = 0; q < 4; q++) bv[q] = bN[q];
        }
        __syncthreads();
    }

    float bn1[8];
#pragma unroll
    for (int j = 0; j < 4; j++) {
        bn1[j * 2 + 0] = __ldg(b1 + warpN + j * 8 + t * 2 + 0);
        bn1[j * 2 + 1] = __ldg(b1 + warpN + j * 8 + t * 2 + 1);
    }
    store_T_frag(Tt, c, bn1, iTb, g, t, warpN, true);
    zero_c(c);
    loadB_frag(bv, B2g, 0, widn, lane);
    __syncthreads();

    // stage 2: T @ B2
    const uint32_t* Ab = Tt + iTb * TI_STR + lane * 4;
#pragma unroll
    for (int ch = 0; ch < 4; ch++) {
        if (ch < 3) loadB_frag(bN, B2g, ch + 1, widn, lane);
        mma_s_bv(Ab + ch * 2 * KS_STR, TI_STR, bv, c);
        if (ch < 3) {
#pragma unroll
            for (int q = 0; q < 4; q++) bv[q] = bN[q];
        }
    }
    __syncthreads();

    // stage-2 epilogue: h += residual; keep hnew resident in T-frag
    float bn2[8];
#pragma unroll
    for (int j = 0; j < 4; j++) {
        bn2[j * 2 + 0] = __ldg(b2 + warpN + j * 8 + t * 2 + 0);
        bn2[j * 2 + 1] = __ldg(b2 + warpN + j * 8 + t * 2 + 1);
    }
    const int ksBase = warpN >> 4;
#pragma unroll
    for (int i = 0; i < 2; i++)
#pragma unroll
        for (int half = 0; half < 2; half++) {
            const int gm = mBase + warpM + i * 16 + g + half * 8;
            const bool ok = gm < N_NODES;
            float* hrow = h + (size_t)gm * 128;
#pragma unroll
            for (int j = 0; j < 4; j++) {
                const int col = warpN + j * 8 + t * 2;
                float v0 = c[i][j][half * 2 + 0] + bn2[j * 2 + 0];
                float v1 = c[i][j][half * 2 + 1] + bn2[j * 2 + 1];
                if (ok) {
                    float2 hv = *reinterpret_cast<const float2*>(hrow + col);
                    v0 += hv.x; v1 += hv.y;
                    *reinterpret_cast<float2*>(hrow + col) = make_float2(v0, v1);
                }
                int ks = ksBase + (j >> 1);
                int w = half + 2 * (j & 1);
                Tt[(iTb + i) * TI_STR + ks * KS_STR + (g * 4 + t) * 4 + w] = h2(v0, v1);
            }
        }

    // stage 3: xOut(half2) = hnew @ lin1next
    if (B3g != nullptr) {
        zero_c(c);
        loadB_frag(bv, B3g, 0, widn, lane);
        __syncthreads();
#pragma unroll
        for (int ch = 0; ch < 4; ch++) {
            if (ch < 3) loadB_frag(bN, B3g, ch + 1, widn, lane);
            mma_s_bv(Ab + ch * 2 * KS_STR, TI_STR, bv, c);
            if (ch < 3) {
#pragma unroll
                for (int q = 0; q < 4; q++) bv[q] = bN[q];
            }
        }
#pragma unroll
        for (int i = 0; i < 2; i++)
#pragma unroll
            for (int half = 0; half < 2; half++) {
                const int gm = mBase + warpM + i * 16 + g + half * 8;
                if (gm < N_NODES) {
                    uint32_t* orow = xOut + (size_t)gm * 64;
#pragma unroll
                    for (int j = 0; j < 4; j++) {
                        const int col = warpN + j * 8 + t * 2;
                        orow[col >> 1] = h2(c[i][j][half * 2 + 0], c[i][j][half * 2 + 1]);
                    }
                }
            }
    }
}

// ---------------- plain GEMM (initial x = h @ lin1_0, half2 out) ------------------
__global__ void __launch_bounds__(NT, 1) gemm_plain(
    const float* __restrict__ A, const uint32_t* __restrict__ Bg,
    uint32_t* __restrict__ out, int M)
{
    extern __shared__ uint32_t sm[];
    uint32_t* As0 = sm;
    uint32_t* As1 = As0 + AWORDS;

    const int tid = threadIdx.x;
    const int wid = tid >> 5, lane = tid & 31;
    const int g = lane >> 2, t = lane & 3;
    const int widm = wid & 3, widn = wid >> 2;
    const int warpM = widm * 32, warpN = widn * 32;
    const int mBase = blockIdx.x * 128;
    const int iTb = widm * 2;

    float c[2][4][4];
    zero_c(c);
    float4 aR[2];
    uint4 bv[4], bN[4];
    loadA_g(aR, A, mBase, 0, M, 128, tid);
    loadB_frag(bv, Bg, 0, widn, lane);
    storeA_f(As0, aR, tid);
    __syncthreads();
#pragma unroll
    for (int ch = 0; ch < 4; ch++) {
        if (ch < 3) {
            loadA_g(aR, A, mBase, (ch + 1) * 32, M, 128, tid);
            loadB_frag(bN, Bg, ch + 1, widn, lane);
        }
        mma_s_bv(((ch & 1) ? As1 : As0) + iTb * AI_STR + lane * 4, AI_STR, bv, c);
        if (ch < 3) {
            storeA_f(((ch + 1) & 1) ? As1 : As0, aR, tid);
#pragma unroll
            for (int q = 0; q < 4; q++) bv[q] = bN[q];
        }
        __syncthreads();
    }
#pragma unroll
    for (int i = 0; i < 2; i++)
#pragma unroll
        for (int half = 0; half < 2; half++) {
            const int gm = mBase + warpM + i * 16 + g + half * 8;
            if (gm < M) {
                uint32_t* orow = out + (size_t)gm * 64;
#pragma unroll
                for (int j = 0; j < 4; j++) {
                    const int col = warpN + j * 8 + t * 2;
                    orow[col >> 1] = h2(c[i][j][half * 2 + 0], c[i][j][half * 2 + 1]);
                }
            }
        }
}

// ---------------- small kernels ----------------
__global__ void embed_kernel(const float* __restrict__ z, const float* __restrict__ w,
                             const float* __restrict__ b, float* __restrict__ h) {
    int n = blockIdx.x, j = threadIdx.x;
    const float* zr = z + (size_t)n * (IN_DIM + HID);
    float acc = b[j] + zr[IN_DIM + j];
#pragma unroll
    for (int k = 0; k < IN_DIM; k++) acc = fmaf(zr[k], w[k * HID + j], acc);
    h[(size_t)n * HID + j] = acc;
}

__global__ void cmask_kernel(const float* __restrict__ len, float* __restrict__ C) {
    int e = blockIdx.x * 256 + threadIdx.x;
    if (e < N_EDGES) {
        float l = len[e];
        C[e] = (l <= 10.0f && l >= 0.0f) ? 1.0f : 0.0f;
    }
}

// ---------------- host launch ----------------
extern "C" void kernel_launch(void* const* d_in, const int* in_sizes, int n_in,
                              void* d_out, int out_size) {
    const float* z      = (const float*)d_in[0];
    const int*   ei     = (const int*)  d_in[1];
    const float* elen   = (const float*)d_in[2];
    const float* eattr  = (const float*)d_in[3];
    const float* emb_w  = (const float*)d_in[4];
    const float* emb_b  = (const float*)d_in[5];
    const float* lin1_w = (const float*)d_in[6];
    const float* nn_w1  = (const float*)d_in[7];
    const float* nn_b1  = (const float*)d_in[8];
    const float* nn_w2  = (const float*)d_in[9];
    const float* nn_b2  = (const float*)d_in[10];
    const float* lin2_w = (const float*)d_in[11];
    const float* lin2_b = (const float*)d_in[12];
    const float* lin_w  = (const float*)d_in[13];
    const float* lin_b  = (const float*)d_in[14];
    float* h = (float*)d_out;

    float *pagg, *pC;
    uint32_t *pxh, *peaf, *pw1, *pw2, *pl2, *pl, *pl1;
    cudaGetSymbolAddress((void**)&pxh,  g_xh);
    cudaGetSymbolAddress((void**)&pagg, g_agg);
    cudaGetSymbolAddress((void**)&pC,   g_C);
    cudaGetSymbolAddress((void**)&peaf, g_eaf);
    cudaGetSymbolAddress((void**)&pw1,  g_w1f);
    cudaGetSymbolAddress((void**)&pw2,  g_w2f);
    cudaGetSymbolAddress((void**)&pl2,  g_l2f);
    cudaGetSymbolAddress((void**)&pl,   g_lf);
    cudaGetSymbolAddress((void**)&pl1,  g_l1f);

    cudaFuncSetAttribute(edge_fused, cudaFuncAttributeMaxDynamicSharedMemorySize, EDGE_SMEM);
    cudaFuncSetAttribute(node_fused, cudaFuncAttributeMaxDynamicSharedMemorySize, NODE_SMEM);
    cudaFuncSetAttribute(gemm_plain, cudaFuncAttributeMaxDynamicSharedMemorySize, PLAIN_SMEM);

    const int* src = ei;
    const int* dst = ei + N_EDGES;

    embed_kernel<<<N_NODES, HID>>>(z, emb_w, emb_b, h);
    cmask_kernel<<<(N_EDGES + 255) / 256, 256>>>(elen, pC);
    pack_eattr<<<NTILES, 256>>>(eattr, peaf);
    {
        dim3 gw((6 * 8192 + 255) / 256, 5);
        pack_w<<<gw, 256>>>(nn_w1, nn_w2, lin2_w, lin_w, lin1_w, pw1, pw2, pl2, pl, pl1);
    }

    const int nodeTiles = (N_NODES + 127) / 128;   // 391

    gemm_plain<<<nodeTiles, NT, PLAIN_SMEM>>>(h, pl1, pxh, N_NODES);

    for (int i = 0; i < N_BLOCKS; i++) {
        edge_fused<<<ETILES, NTE, EDGE_SMEM>>>(
            peaf, pw1 + i * 8192, nn_b1 + (size_t)i * HID,
            pw2 + i * 8192, nn_b2 + (size_t)i * HID,
            pC, src, dst, pxh, pagg);
        const uint32_t* lin1next = (i + 1 < N_BLOCKS) ? (pl1 + (i + 1) * 8192) : nullptr;
        node_fused<<<nodeTiles, NT, NODE_SMEM>>>(
            pagg, pagg, pl2 + i * 8192, lin2_b + (size_t)i * HID,
            pl + i * 8192, lin_b + (size_t)i * HID,
            h, lin1next, pxh);
    }
}

// round 16
// speedup vs baseline: 1.4382x; 1.0183x over previous
#include <cuda_runtime.h>
#include <cuda_fp16.h>
#include <cstdint>
#include <math.h>

#define N_NODES 50000
#define N_EDGES 800000
#define HID 128
#define EC 100
#define IN_DIM 5
#define N_BLOCKS 6
#define NTE 256
#define NTILES 6250
#define ETILES 12500
#define NODETILES 782   // ceil(50000/64)

// ---------------- scratch (device globals; no runtime allocation) ----------------
__device__ uint32_t g_xh[N_NODES * 64];        // x in half2
__device__ float g_agg[N_NODES * HID];         // zero-init (BSS); launches return it to zero
__device__ float g_C[N_EDGES];
__device__ uint32_t g_eaf[(size_t)NTILES * 8192];   // eattr fragment-order fp16
__device__ uint32_t g_w1f[6 * 8192];
__device__ uint32_t g_w2f[6 * 8192];
__device__ uint32_t g_l2f[6 * 8192];
__device__ uint32_t g_lf [6 * 8192];
__device__ uint32_t g_l1f[6 * 8192];

__device__ __forceinline__ float sspf(float x) {
    float sp = fmaxf(x, 0.0f) + log1pf(expf(-fabsf(x)));
    return sp - 0.69314718055994531f;
}
__device__ __forceinline__ uint32_t h2(float lo, float hi) {
    uint32_t r;
    asm("cvt.rn.f16x2.f32 %0, %1, %2;" : "=r"(r) : "f"(hi), "f"(lo));
    return r;
}

// ---------------- fragment layout constants ----------------
#define KS_STR 132
#define AI_STR 264
#define AWORDS_N 1056          // 4 i-tiles (64 rows) per chunk buffer
#define TI_STR 1056
#define TWORDS_N 4224          // 64-row T tile
#define WS_STR 68
#define WWORDS_E (64 * WS_STR)

#define EDGE_SMEM (WWORDS_E * 4)                    // 17408
#define NODE_SMEM ((TWORDS_N + 2 * AWORDS_N) * 4)   // 25344
#define PLAIN_SMEM ((2 * AWORDS_N) * 4)             // 8448

// ---------------- weight pre-pack ----------------
__global__ void __launch_bounds__(256) pack_w(
    const float* __restrict__ w1, const float* __restrict__ w2,
    const float* __restrict__ l2, const float* __restrict__ l,
    const float* __restrict__ l1,
    uint32_t* __restrict__ o1, uint32_t* __restrict__ o2,
    uint32_t* __restrict__ o3, uint32_t* __restrict__ o4,
    uint32_t* __restrict__ o5)
{
    const float* W; uint32_t* O; int K;
    switch (blockIdx.y) {
        case 0: W = w1; O = o1; K = EC;  break;
        case 1: W = w2; O = o2; K = 128; break;
        case 2: W = l2; O = o3; K = 128; break;
        case 3: W = l;  O = o4; K = 128; break;
        default: W = l1; O = o5; K = 128; break;
    }
    int idx = blockIdx.x * 256 + threadIdx.x;
    if (idx >= 6 * 8192) return;
    int blk = idx >> 13;
    int r = idx & 8191;
    int ch = r >> 11;
    int r2 = r & 2047;
    int pair = r2 >> 8;
    int ks = (r2 >> 7) & 1;
    int lane = (r2 >> 2) & 31;
    int w = r2 & 3;
    int g0 = lane >> 2, t = lane & 3;
    int jpar = w >> 1, wb = w & 1;
    int k = ch * 32 + ks * 16 + wb * 8 + t * 2;
    int n = pair * 16 + jpar * 8 + g0;
    const float* Wb = W + (size_t)blk * K * 128;
    float v0 = (k < K) ? Wb[(size_t)k * 128 + n] : 0.f;
    float v1 = (k + 1 < K) ? Wb[(size_t)(k + 1) * 128 + n] : 0.f;
    O[idx] = h2(v0, v1);
}

// ---------------- A loaders (64-row tile, 256 threads) ----------------
__device__ __forceinline__ void loadA_g(float4* r, const float* __restrict__ A,
                                        int mBase, int k0, int M, int K, int tid) {
#pragma unroll
    for (int i = 0; i < 2; i++) {
        int q = tid + (i << 8);
        int row = q >> 3, kq = (q & 7) << 2;
        int gm = mBase + row, gk = k0 + kq;
        r[i] = make_float4(0.f, 0.f, 0.f, 0.f);
        if (gm < M && gk < K)
            r[i] = *reinterpret_cast<const float4*>(A + (size_t)gm * K + gk);
    }
}
__device__ __forceinline__ void zeroA_g(float* __restrict__ A, int mBase, int k0,
                                        int M, int K, int tid) {
#pragma unroll
    for (int i = 0; i < 2; i++) {
        int q = tid + (i << 8);
        int row = q >> 3, kq = (q & 7) << 2;
        int gm = mBase + row, gk = k0 + kq;
        if (gm < M && gk < K)
            *reinterpret_cast<float4*>(A + (size_t)gm * K + gk) =
                make_float4(0.f, 0.f, 0.f, 0.f);
    }
}
__device__ __forceinline__ void storeA_f(uint32_t* __restrict__ buf, const float4* r, int tid) {
#pragma unroll
    for (int i4 = 0; i4 < 2; i4++) {
        int q = tid + (i4 << 8);
        int row = q >> 3, kq = (q & 7) << 2;
        int iT = row >> 4, rl = row & 15;
        int g = rl & 7, hr = rl >> 3;
        int ks = kq >> 4, kl = kq & 15;
        int w = hr + ((kl & 8) ? 2 : 0);
        int t0 = (kl & 7) >> 1;
        uint32_t* p = buf + iT * AI_STR + ks * KS_STR + (g * 4 + t0) * 4 + w;
        p[0] = h2(r[i4].x, r[i4].y);
        p[4] = h2(r[i4].z, r[i4].w);
    }
}

// ---------------- fragment loads ----------------
__device__ __forceinline__ void loadB_frag(uint4* bv, const uint32_t* __restrict__ Bg,
                                           int ch, int widn, int lane) {
    const uint32_t* Bb = Bg + ch * 2048 + (widn * 2) * 256 + lane * 4;
#pragma unroll
    for (int ks = 0; ks < 2; ks++)
#pragma unroll
        for (int p = 0; p < 2; p++)
            bv[ks * 2 + p] = *reinterpret_cast<const uint4*>(Bb + p * 256 + ks * 128);
}
__device__ __forceinline__ void loadAe_frag(uint4* av, const uint32_t* __restrict__ Af, int ch) {
#pragma unroll
    for (int s = 0; s < 2; s++)
#pragma unroll
        for (int i = 0; i < 2; i++)
            av[s * 2 + i] = *reinterpret_cast<const uint4*>(Af + i * 1024 + (ch * 2 + s) * 128);
}

// ---------------- mma ----------------
__device__ __forceinline__ void mma8(float c[4][4], const uint4 av, const uint4* bv) {
#pragma unroll
    for (int j = 0; j < 4; j++) {
        uint32_t b0 = (j & 1) ? bv[j >> 1].z : bv[j >> 1].x;
        uint32_t b1 = (j & 1) ? bv[j >> 1].w : bv[j >> 1].y;
        asm volatile(
            "mma.sync.aligned.m16n8k16.row.col.f32.f16.f16.f32 "
            "{%0,%1,%2,%3}, {%4,%5,%6,%7}, {%8,%9}, {%0,%1,%2,%3};\n"
            : "+f"(c[j][0]), "+f"(c[j][1]), "+f"(c[j][2]), "+f"(c[j][3])
            : "r"(av.x), "r"(av.y), "r"(av.z), "r"(av.w), "r"(b0), "r"(b1));
    }
}
__device__ __forceinline__ void mma_bv(float c[2][4][4], const uint4* aC, const uint4* bv) {
#pragma unroll
    for (int ks = 0; ks < 2; ks++)
#pragma unroll
        for (int i = 0; i < 2; i++)
            mma8(c[i], aC[ks * 2 + i], &bv[ks * 2]);
}
__device__ __forceinline__ void mma_s_bv(const uint32_t* __restrict__ Ab, int istr,
                                         const uint4* bv, float c[2][4][4])
{
#pragma unroll
    for (int ks = 0; ks < 2; ks++) {
        uint4 av[2];
#pragma unroll
        for (int i = 0; i < 2; i++)
            av[i] = *reinterpret_cast<const uint4*>(Ab + i * istr + ks * KS_STR);
#pragma unroll
        for (int i = 0; i < 2; i++)
            mma8(c[i], av[i], &bv[ks * 2]);
    }
}

__device__ __forceinline__ void zero_c(float c[2][4][4]) {
#pragma unroll
    for (int i = 0; i < 2; i++)
#pragma unroll
        for (int j = 0; j < 4; j++)
#pragma unroll
            for (int v = 0; v < 4; v++) c[i][j][v] = 0.0f;
}

__device__ __forceinline__ void store_T_frag(uint32_t* __restrict__ Tt, const float c[2][4][4],
                                             const float* bn, int iTb, int g, int t,
                                             int warpN, bool doSsp)
{
    const int ksBase = warpN >> 4;
#pragma unroll
    for (int i = 0; i < 2; i++)
#pragma unroll
        for (int half = 0; half < 2; half++)
#pragma unroll
            for (int j = 0; j < 4; j++) {
                float v0 = c[i][j][half * 2 + 0] + bn[j * 2 + 0];
                float v1 = c[i][j][half * 2 + 1] + bn[j * 2 + 1];
                if (doSsp) { v0 = sspf(v0); v1 = sspf(v1); }
                int ks = ksBase + (j >> 1);
                int w = half + 2 * (j & 1);
                Tt[(iTb + i) * TI_STR + ks * KS_STR + (g * 4 + t) * 4 + w] = h2(v0, v1);
            }
}

// ---------------- eattr pre-pack (tile-staged, coalesced; proven R9/R11) ----------
__global__ void __launch_bounds__(256) pack_eattr(const float* __restrict__ ea,
                                                  uint32_t* __restrict__ out) {
    __shared__ uint32_t sf[8192];
    const int tile = blockIdx.x;
    const int tid = threadIdx.x;
    const int row = tid >> 1;
    const int kh = tid & 1;
    const float* er = ea + ((size_t)tile * 128 + row) * EC;
    const int iT = row >> 4, rl = row & 15;
    const int g = rl & 7, hr = rl >> 3;
#pragma unroll
    for (int q = 0; q < 4; q++) {
#pragma unroll
        for (int f4 = 0; f4 < 4; f4++) {
            int kq = kh * 64 + (q * 4 + f4) * 4;
            float4 v = make_float4(0.f, 0.f, 0.f, 0.f);
            if (kq < EC) {
                if (kq + 3 < EC)
                    v = *reinterpret_cast<const float4*>(er + kq);
                else {
                    v.x = er[kq];
                    if (kq + 1 < EC) v.y = er[kq + 1];
                    if (kq + 2 < EC) v.z = er[kq + 2];
                }
            }
            int ks = kq >> 4, kl = kq & 15;
            int w = hr + ((kl & 8) ? 2 : 0);
            int t0 = (kl & 7) >> 1;
            uint32_t* p = sf + iT * 1024 + ks * 128 + (g * 4 + t0) * 4 + w;
            p[0] = h2(v.x, v.y);
            p[4] = h2(v.z, v.w);
        }
    }
    __syncthreads();
    uint32_t* o = out + (size_t)tile * 8192;
#pragma unroll
    for (int i = 0; i < 8; i++)
        *reinterpret_cast<uint4*>(o + (tid + i * 256) * 4) =
            *reinterpret_cast<const uint4*>(sf + (tid + i * 256) * 4);
}

// ---------------- fused edge kernel: 64-edge tiles, 256 threads, 2 CTAs/SM --------
__global__ void __launch_bounds__(NTE, 2) edge_fused(
    const uint32_t* __restrict__ eaf,
    const uint32_t* __restrict__ B1g, const float* __restrict__ b1,
    const uint32_t* __restrict__ B2g, const float* __restrict__ b2,
    const float* __restrict__ Cm, const int* __restrict__ src, const int* __restrict__ dst,
    const uint32_t* __restrict__ xh, float* __restrict__ agg)
{
    extern __shared__ uint32_t sm[];
    uint32_t* Tt = sm;
    uint32_t* Wm = sm;

    const int tid = threadIdx.x;
    const int wid = tid >> 5, lane = tid & 31;
    const int g = lane >> 2, t = lane & 3;
    const int widm = wid & 1, widn = wid >> 1;
    const int warpM = widm * 32, warpN = widn * 32;
    const int mBase = blockIdx.x * 64;
    const int iTb = widm * 2;

    float c[2][4][4];
    zero_c(c);

    const uint32_t* Af = eaf + (size_t)(blockIdx.x >> 1) * 8192
                       + ((blockIdx.x & 1) * 4 + widm * 2) * 1024 + lane * 4;
    uint4 aC[4], bv[4], aN[4], bN[4];
    loadAe_frag(aC, Af, 0);
    loadB_frag(bv, B1g, 0, widn, lane);
#pragma unroll
    for (int ch = 0; ch < 4; ch++) {
        if (ch < 3) {
            loadAe_frag(aN, Af, ch + 1);
            loadB_frag(bN, B1g, ch + 1, widn, lane);
        }
        mma_bv(c, aC, bv);
        if (ch < 3) {
#pragma unroll
            for (int q = 0; q < 4; q++) { aC[q] = aN[q]; bv[q] = bN[q]; }
        }
    }

    float bn1[8];
#pragma unroll
    for (int j = 0; j < 4; j++) {
        bn1[j * 2 + 0] = __ldg(b1 + warpN + j * 8 + t * 2 + 0);
        bn1[j * 2 + 1] = __ldg(b1 + warpN + j * 8 + t * 2 + 1);
    }
    store_T_frag(Tt, c, bn1, iTb, g, t, warpN, true);
    zero_c(c);
    loadB_frag(bv, B2g, 0, widn, lane);
    __syncthreads();

    const uint32_t* Ab = Tt + iTb * TI_STR + lane * 4;
#pragma unroll
    for (int ch = 0; ch < 4; ch++) {
        if (ch < 3) loadB_frag(bN, B2g, ch + 1, widn, lane);
        mma_s_bv(Ab + ch * 2 * KS_STR, TI_STR, bv, c);
        if (ch < 3) {
#pragma unroll
            for (int q = 0; q < 4; q++) bv[q] = bN[q];
        }
    }
    __syncthreads();

    float bn2[8];
#pragma unroll
    for (int j = 0; j < 4; j++) {
        bn2[j * 2 + 0] = __ldg(b2 + warpN + j * 8 + t * 2 + 0);
        bn2[j * 2 + 1] = __ldg(b2 + warpN + j * 8 + t * 2 + 1);
    }
#pragma unroll
    for (int i = 0; i < 2; i++)
#pragma unroll
        for (int half = 0; half < 2; half++) {
            const int row = warpM + i * 16 + g + half * 8;
#pragma unroll
            for (int j = 0; j < 4; j++) {
                float v0 = c[i][j][half * 2 + 0] + bn2[j * 2 + 0];
                float v1 = c[i][j][half * 2 + 1] + bn2[j * 2 + 1];
                Wm[row * WS_STR + (warpN >> 1) + j * 4 + t] = h2(v0, v1);
            }
        }
    __syncthreads();

#pragma unroll
    for (int it = 0; it < 8; it++) {
        const int e = mBase + wid * 8 + it;
        const float cmv = __ldg(Cm + e);
        if (cmv != 0.0f) {
            const int s = __ldg(src + e);
            const int d = __ldg(dst + e);
            uint2 Wp = *reinterpret_cast<const uint2*>(Wm + (wid * 8 + it) * WS_STR + lane * 2);
            uint2 xp = __ldg(reinterpret_cast<const uint2*>(xh + (size_t)s * 64 + lane * 2));
            float2 w01 = __half22float2(*reinterpret_cast<const __half2*>(&Wp.x));
            float2 w23 = __half22float2(*reinterpret_cast<const __half2*>(&Wp.y));
            float2 x01 = __half22float2(*reinterpret_cast<const __half2*>(&xp.x));
            float2 x23 = __half22float2(*reinterpret_cast<const __half2*>(&xp.y));
            float m0 = x01.x * w01.x, m1 = x01.y * w01.y;
            float m2 = x23.x * w23.x, m3 = x23.y * w23.y;
            asm volatile("red.global.add.v4.f32 [%0], {%1, %2, %3, %4};"
                         :: "l"(agg + (size_t)d * 128 + lane * 4),
                            "f"(m0), "f"(m1), "f"(m2), "f"(m3) : "memory");
        }
    }
}

// ---------------- fused node kernel: 64-row tiles, 256 threads, 2 CTAs/SM ---------
__global__ void __launch_bounds__(NTE, 2) node_fused(
    const float* __restrict__ agg, float* __restrict__ aggW,
    const uint32_t* __restrict__ B1g, const float* __restrict__ b1,
    const uint32_t* __restrict__ B2g, const float* __restrict__ b2,
    float* __restrict__ h, const uint32_t* __restrict__ B3g, uint32_t* __restrict__ xOut)
{
    extern __shared__ uint32_t sm[];
    uint32_t* Tt  = sm;
    uint32_t* As0 = sm + TWORDS_N;
    uint32_t* As1 = As0 + AWORDS_N;

    const int tid = threadIdx.x;
    const int wid = tid >> 5, lane = tid & 31;
    const int g = lane >> 2, t = lane & 3;
    const int widm = wid & 1, widn = wid >> 1;
    const int warpM = widm * 32, warpN = widn * 32;
    const int mBase = blockIdx.x * 64;
    const int iTb = widm * 2;

    float c[2][4][4];
    zero_c(c);
    float4 aR[2];
    uint4 bv[4], bN[4];

    // stage 1: agg (smem-staged, double-buffered) @ B1; zero agg behind the read
    loadA_g(aR, agg, mBase, 0, N_NODES, 128, tid);
    zeroA_g(aggW, mBase, 0, N_NODES, 128, tid);
    loadB_frag(bv, B1g, 0, widn, lane);
    storeA_f(As0, aR, tid);
    __syncthreads();
#pragma unroll
    for (int ch = 0; ch < 4; ch++) {
        if (ch < 3) {
            loadA_g(aR, agg, mBase, (ch + 1) * 32, N_NODES, 128, tid);
            zeroA_g(aggW, mBase, (ch + 1) * 32, N_NODES, 128, tid);
            loadB_frag(bN, B1g, ch + 1, widn, lane);
        }
        mma_s_bv(((ch & 1) ? As1 : As0) + iTb * AI_STR + lane * 4, AI_STR, bv, c);
        if (ch < 3) {
            storeA_f(((ch + 1) & 1) ? As1 : As0, aR, tid);
#pragma unroll
            for (int q = 0; q < 4; q++) bv[q] = bN[q];
        }
        __syncthreads();
    }

    float bn1[8];
#pragma unroll
    for (int j = 0; j < 4; j++) {
        bn1[j * 2 + 0] = __ldg(b1 + warpN + j * 8 + t * 2 + 0);
        bn1[j * 2 + 1] = __ldg(b1 + warpN + j * 8 + t * 2 + 1);
    }
    store_T_frag(Tt, c, bn1, iTb, g, t, warpN, true);
    zero_c(c);
    loadB_frag(bv, B2g, 0, widn, lane);
    __syncthreads();

    // stage 2: T @ B2
    const uint32_t* Ab = Tt + iTb * TI_STR + lane * 4;
#pragma unroll
    for (int ch = 0; ch < 4; ch++) {
        if (ch < 3) loadB_frag(bN, B2g, ch + 1, widn, lane);
        mma_s_bv(Ab + ch * 2 * KS_STR, TI_STR, bv, c);
        if (ch < 3) {
#pragma unroll
            for (int q = 0; q < 4; q++) bv[q] = bN[q];
        }
    }
    __syncthreads();

    // stage-2 epilogue: h += residual; keep hnew resident in T-frag
    float bn2[8];
#pragma unroll
    for (int j = 0; j < 4; j++) {
        bn2[j * 2 + 0] = __ldg(b2 + warpN + j * 8 + t * 2 + 0);
        bn2[j * 2 + 1] = __ldg(b2 + warpN + j * 8 + t * 2 + 1);
    }
    const int ksBase = warpN >> 4;
#pragma unroll
    for (int i = 0; i < 2; i++)
#pragma unroll
        for (int half = 0; half < 2; half++) {
            const int gm = mBase + warpM + i * 16 + g + half * 8;
            const bool ok = gm < N_NODES;
            float* hrow = h + (size_t)gm * 128;
#pragma unroll
            for (int j = 0; j < 4; j++) {
                const int col = warpN + j * 8 + t * 2;
                float v0 = c[i][j][half * 2 + 0] + bn2[j * 2 + 0];
                float v1 = c[i][j][half * 2 + 1] + bn2[j * 2 + 1];
                if (ok) {
                    float2 hv = *reinterpret_cast<const float2*>(hrow + col);
                    v0 += hv.x; v1 += hv.y;
                    *reinterpret_cast<float2*>(hrow + col) = make_float2(v0, v1);
                }
                int ks = ksBase + (j >> 1);
                int w = half + 2 * (j & 1);
                Tt[(iTb + i) * TI_STR + ks * KS_STR + (g * 4 + t) * 4 + w] = h2(v0, v1);
            }
        }

    // stage 3: xOut(half2) = hnew @ lin1next
    if (B3g != nullptr) {
        zero_c(c);
        loadB_frag(bv, B3g, 0, widn, lane);
        __syncthreads();
#pragma unroll
        for (int ch = 0; ch < 4; ch++) {
            if (ch < 3) loadB_frag(bN, B3g, ch + 1, widn, lane);
            mma_s_bv(Ab + ch * 2 * KS_STR, TI_STR, bv, c);
            if (ch < 3) {
#pragma unroll
                for (int q = 0; q < 4; q++) bv[q] = bN[q];
            }
        }
#pragma unroll
        for (int i = 0; i < 2; i++)
#pragma unroll
            for (int half = 0; half < 2; half++) {
                const int gm = mBase + warpM + i * 16 + g + half * 8;
                if (gm < N_NODES) {
                    uint32_t* orow = xOut + (size_t)gm * 64;
#pragma unroll
                    for (int j = 0; j < 4; j++) {
                        const int col = warpN + j * 8 + t * 2;
                        orow[col >> 1] = h2(c[i][j][half * 2 + 0], c[i][j][half * 2 + 1]);
                    }
                }
            }
    }
}

// ---------------- plain GEMM: 64-row tiles, 256 threads, 2 CTAs/SM ----------------
__global__ void __launch_bounds__(NTE, 2) gemm_plain(
    const float* __restrict__ A, const uint32_t* __restrict__ Bg,
    uint32_t* __restrict__ out, int M)
{
    extern __shared__ uint32_t sm[];
    uint32_t* As0 = sm;
    uint32_t* As1 = As0 + AWORDS_N;

    const int tid = threadIdx.x;
    const int wid = tid >> 5, lane = tid & 31;
    const int g = lane >> 2, t = lane & 3;
    const int widm = wid & 1, widn = wid >> 1;
    const int warpM = widm * 32, warpN = widn * 32;
    const int mBase = blockIdx.x * 64;
    const int iTb = widm * 2;

    float c[2][4][4];
    zero_c(c);
    float4 aR[2];
    uint4 bv[4], bN[4];
    loadA_g(aR, A, mBase, 0, M, 128, tid);
    loadB_frag(bv, Bg, 0, widn, lane);
    storeA_f(As0, aR, tid);
    __syncthreads();
#pragma unroll
    for (int ch = 0; ch < 4; ch++) {
        if (ch < 3) {
            loadA_g(aR, A, mBase, (ch + 1) * 32, M, 128, tid);
            loadB_frag(bN, Bg, ch + 1, widn, lane);
        }
        mma_s_bv(((ch & 1) ? As1 : As0) + iTb * AI_STR + lane * 4, AI_STR, bv, c);
        if (ch < 3) {
            storeA_f(((ch + 1) & 1) ? As1 : As0, aR, tid);
#pragma unroll
            for (int q = 0; q < 4; q++) bv[q] = bN[q];
        }
        __syncthreads();
    }
#pragma unroll
    for (int i = 0; i < 2; i++)
#pragma unroll
        for (int half = 0; half < 2; half++) {
            const int gm = mBase + warpM + i * 16 + g + half * 8;
            if (gm < M) {
                uint32_t* orow = out + (size_t)gm * 64;
#pragma unroll
                for (int j = 0; j < 4; j++) {
                    const int col = warpN + j * 8 + t * 2;
                    orow[col >> 1] = h2(c[i][j][half * 2 + 0], c[i][j][half * 2 + 1]);
                }
            }
        }
}

// ---------------- small kernels ----------------
__global__ void embed_kernel(const float* __restrict__ z, const float* __restrict__ w,
                             const float* __restrict__ b, float* __restrict__ h) {
    int n = blockIdx.x, j = threadIdx.x;
    const float* zr = z + (size_t)n * (IN_DIM + HID);
    float acc = b[j] + zr[IN_DIM + j];
#pragma unroll
    for (int k = 0; k < IN_DIM; k++) acc = fmaf(zr[k], w[k * HID + j], acc);
    h[(size_t)n * HID + j] = acc;
}

__global__ void cmask_kernel(const float* __restrict__ len, float* __restrict__ C) {
    int e = blockIdx.x * 256 + threadIdx.x;
    if (e < N_EDGES) {
        float l = len[e];
        C[e] = (l <= 10.0f && l >= 0.0f) ? 1.0f : 0.0f;
    }
}

// ---------------- host launch ----------------
extern "C" void kernel_launch(void* const* d_in, const int* in_sizes, int n_in,
                              void* d_out, int out_size) {
    const float* z      = (const float*)d_in[0];
    const int*   ei     = (const int*)  d_in[1];
    const float* elen   = (const float*)d_in[2];
    const float* eattr  = (const float*)d_in[3];
    const float* emb_w  = (const float*)d_in[4];
    const float* emb_b  = (const float*)d_in[5];
    const float* lin1_w = (const float*)d_in[6];
    const float* nn_w1  = (const float*)d_in[7];
    const float* nn_b1  = (const float*)d_in[8];
    const float* nn_w2  = (const float*)d_in[9];
    const float* nn_b2  = (const float*)d_in[10];
    const float* lin2_w = (const float*)d_in[11];
    const float* lin2_b = (const float*)d_in[12];
    const float* lin_w  = (const float*)d_in[13];
    const float* lin_b  = (const float*)d_in[14];
    float* h = (float*)d_out;

    float *pagg, *pC;
    uint32_t *pxh, *peaf, *pw1, *pw2, *pl2, *pl, *pl1;
    cudaGetSymbolAddress((void**)&pxh,  g_xh);
    cudaGetSymbolAddress((void**)&pagg, g_agg);
    cudaGetSymbolAddress((void**)&pC,   g_C);
    cudaGetSymbolAddress((void**)&peaf, g_eaf);
    cudaGetSymbolAddress((void**)&pw1,  g_w1f);
    cudaGetSymbolAddress((void**)&pw2,  g_w2f);
    cudaGetSymbolAddress((void**)&pl2,  g_l2f);
    cudaGetSymbolAddress((void**)&pl,   g_lf);
    cudaGetSymbolAddress((void**)&pl1,  g_l1f);

    cudaFuncSetAttribute(edge_fused, cudaFuncAttributeMaxDynamicSharedMemorySize, EDGE_SMEM);
    cudaFuncSetAttribute(node_fused, cudaFuncAttributeMaxDynamicSharedMemorySize, NODE_SMEM);
    cudaFuncSetAttribute(gemm_plain, cudaFuncAttributeMaxDynamicSharedMemorySize, PLAIN_SMEM);

    const int* src = ei;
    const int* dst = ei + N_EDGES;

    embed_kernel<<<N_NODES, HID>>>(z, emb_w, emb_b, h);
    cmask_kernel<<<(N_EDGES + 255) / 256, 256>>>(elen, pC);
    pack_eattr<<<NTILES, 256>>>(eattr, peaf);
    {
        dim3 gw((6 * 8192 + 255) / 256, 5);
        pack_w<<<gw, 256>>>(nn_w1, nn_w2, lin2_w, lin_w, lin1_w, pw1, pw2, pl2, pl, pl1);
    }

    gemm_plain<<<NODETILES, NTE, PLAIN_SMEM>>>(h, pl1, pxh, N_NODES);

    for (int i = 0; i < N_BLOCKS; i++) {
        edge_fused<<<ETILES, NTE, EDGE_SMEM>>>(
            peaf, pw1 + i * 8192, nn_b1 + (size_t)i * HID,
            pw2 + i * 8192, nn_b2 + (size_t)i * HID,
            pC, src, dst, pxh, pagg);
        const uint32_t* lin1next = (i + 1 < N_BLOCKS) ? (pl1 + (i + 1) * 8192) : nullptr;
        node_fused<<<NODETILES, NTE, NODE_SMEM>>>(
            pagg, pagg, pl2 + i * 8192, lin2_b + (size_t)i * HID,
            pl + i * 8192, lin_b + (size_t)i * HID,
            h, lin1next, pxh);
    }
}

// round 17
// speedup vs baseline: 1.6227x; 1.1283x over previous
#include <cuda_runtime.h>
#include <cuda_fp16.h>
#include <cstdint>
#include <math.h>

#define N_NODES 50000
#define N_EDGES 800000
#define HID 128
#define EC 100
#define IN_DIM 5
#define N_BLOCKS 6
#define NTE 256
#define NTILES 6250
#define ETILES 12500
#define NODETILES 782   // ceil(50000/64)

// ---------------- scratch (device globals; no runtime allocation) ----------------
__device__ uint32_t g_xh[N_NODES * 64];        // x in half2
__device__ float g_agg[N_NODES * HID];         // zero-init (BSS); launches return it to zero
__device__ int2 g_meta[N_EDGES];               // (src | -1 if masked, dst)
__device__ uint32_t g_eaf[(size_t)NTILES * 8192];   // eattr fragment-order fp16
__device__ uint32_t g_w1f[6 * 8192];
__device__ uint32_t g_w2f[6 * 8192];
__device__ uint32_t g_l2f[6 * 8192];
__device__ uint32_t g_lf [6 * 8192];
__device__ uint32_t g_l1f[6 * 8192];

__device__ __forceinline__ float sspf(float x) {
    float sp = fmaxf(x, 0.0f) + log1pf(expf(-fabsf(x)));
    return sp - 0.69314718055994531f;
}
__device__ __forceinline__ uint32_t h2(float lo, float hi) {
    uint32_t r;
    asm("cvt.rn.f16x2.f32 %0, %1, %2;" : "=r"(r) : "f"(hi), "f"(lo));
    return r;
}

// ---------------- fragment layout constants ----------------
#define KS_STR 132
#define AI_STR 264
#define AWORDS_N 1056
#define TI_STR 1056
#define TWORDS_N 4224
#define WS_STR 68
#define WWORDS_E (64 * WS_STR)

#define EDGE_SMEM (WWORDS_E * 4)
#define NODE_SMEM ((TWORDS_N + 2 * AWORDS_N) * 4)
#define PLAIN_SMEM ((2 * AWORDS_N) * 4)

// ---------------- weight pre-pack ----------------
__global__ void __launch_bounds__(256) pack_w(
    const float* __restrict__ w1, const float* __restrict__ w2,
    const float* __restrict__ l2, const float* __restrict__ l,
    const float* __restrict__ l1,
    uint32_t* __restrict__ o1, uint32_t* __restrict__ o2,
    uint32_t* __restrict__ o3, uint32_t* __restrict__ o4,
    uint32_t* __restrict__ o5)
{
    const float* W; uint32_t* O; int K;
    switch (blockIdx.y) {
        case 0: W = w1; O = o1; K = EC;  break;
        case 1: W = w2; O = o2; K = 128; break;
        case 2: W = l2; O = o3; K = 128; break;
        case 3: W = l;  O = o4; K = 128; break;
        default: W = l1; O = o5; K = 128; break;
    }
    int idx = blockIdx.x * 256 + threadIdx.x;
    if (idx >= 6 * 8192) return;
    int blk = idx >> 13;
    int r = idx & 8191;
    int ch = r >> 11;
    int r2 = r & 2047;
    int pair = r2 >> 8;
    int ks = (r2 >> 7) & 1;
    int lane = (r2 >> 2) & 31;
    int w = r2 & 3;
    int g0 = lane >> 2, t = lane & 3;
    int jpar = w >> 1, wb = w & 1;
    int k = ch * 32 + ks * 16 + wb * 8 + t * 2;
    int n = pair * 16 + jpar * 8 + g0;
    const float* Wb = W + (size_t)blk * K * 128;
    float v0 = (k < K) ? Wb[(size_t)k * 128 + n] : 0.f;
    float v1 = (k + 1 < K) ? Wb[(size_t)(k + 1) * 128 + n] : 0.f;
    O[idx] = h2(v0, v1);
}

// ---------------- A loaders (64-row tile, 256 threads) ----------------
__device__ __forceinline__ void loadA_g(float4* r, const float* __restrict__ A,
                                        int mBase, int k0, int M, int K, int tid) {
#pragma unroll
    for (int i = 0; i < 2; i++) {
        int q = tid + (i << 8);
        int row = q >> 3, kq = (q & 7) << 2;
        int gm = mBase + row, gk = k0 + kq;
        r[i] = make_float4(0.f, 0.f, 0.f, 0.f);
        if (gm < M && gk < K)
            r[i] = *reinterpret_cast<const float4*>(A + (size_t)gm * K + gk);
    }
}
__device__ __forceinline__ void zeroA_g(float* __restrict__ A, int mBase, int k0,
                                        int M, int K, int tid) {
#pragma unroll
    for (int i = 0; i < 2; i++) {
        int q = tid + (i << 8);
        int row = q >> 3, kq = (q & 7) << 2;
        int gm = mBase + row, gk = k0 + kq;
        if (gm < M && gk < K)
            *reinterpret_cast<float4*>(A + (size_t)gm * K + gk) =
                make_float4(0.f, 0.f, 0.f, 0.f);
    }
}
__device__ __forceinline__ void storeA_f(uint32_t* __restrict__ buf, const float4* r, int tid) {
#pragma unroll
    for (int i4 = 0; i4 < 2; i4++) {
        int q = tid + (i4 << 8);
        int row = q >> 3, kq = (q & 7) << 2;
        int iT = row >> 4, rl = row & 15;
        int g = rl & 7, hr = rl >> 3;
        int ks = kq >> 4, kl = kq & 15;
        int w = hr + ((kl & 8) ? 2 : 0);
        int t0 = (kl & 7) >> 1;
        uint32_t* p = buf + iT * AI_STR + ks * KS_STR + (g * 4 + t0) * 4 + w;
        p[0] = h2(r[i4].x, r[i4].y);
        p[4] = h2(r[i4].z, r[i4].w);
    }
}

// ---------------- fragment loads ----------------
__device__ __forceinline__ void loadB_frag(uint4* bv, const uint32_t* __restrict__ Bg,
                                           int ch, int widn, int lane) {
    const uint32_t* Bb = Bg + ch * 2048 + (widn * 2) * 256 + lane * 4;
#pragma unroll
    for (int ks = 0; ks < 2; ks++)
#pragma unroll
        for (int p = 0; p < 2; p++)
            bv[ks * 2 + p] = *reinterpret_cast<const uint4*>(Bb + p * 256 + ks * 128);
}
// kstep-granular loads (edge path)
__device__ __forceinline__ void ldA_e(uint4* a, const uint32_t* __restrict__ AfB, int ks) {
    a[0] = *reinterpret_cast<const uint4*>(AfB + ks * 128);
    a[1] = *reinterpret_cast<const uint4*>(AfB + 1024 + ks * 128);
}
__device__ __forceinline__ void ldB_k(uint4* b, const uint32_t* __restrict__ BgB, int ks) {
    const uint32_t* p = BgB + (ks >> 1) * 2048 + (ks & 1) * 128;
    b[0] = *reinterpret_cast<const uint4*>(p);
    b[1] = *reinterpret_cast<const uint4*>(p + 256);
}
__device__ __forceinline__ void ldA_s(uint4* a, const uint32_t* __restrict__ Ab, int ks) {
    a[0] = *reinterpret_cast<const uint4*>(Ab + ks * KS_STR);
    a[1] = *reinterpret_cast<const uint4*>(Ab + TI_STR + ks * KS_STR);
}

// ---------------- mma ----------------
__device__ __forceinline__ void mma8(float c[4][4], const uint4 av, const uint4* bv) {
#pragma unroll
    for (int j = 0; j < 4; j++) {
        uint32_t b0 = (j & 1) ? bv[j >> 1].z : bv[j >> 1].x;
        uint32_t b1 = (j & 1) ? bv[j >> 1].w : bv[j >> 1].y;
        asm volatile(
            "mma.sync.aligned.m16n8k16.row.col.f32.f16.f16.f32 "
            "{%0,%1,%2,%3}, {%4,%5,%6,%7}, {%8,%9}, {%0,%1,%2,%3};\n"
            : "+f"(c[j][0]), "+f"(c[j][1]), "+f"(c[j][2]), "+f"(c[j][3])
            : "r"(av.x), "r"(av.y), "r"(av.z), "r"(av.w), "r"(b0), "r"(b1));
    }
}
__device__ __forceinline__ void mma_s_bv(const uint32_t* __restrict__ Ab, int istr,
                                         const uint4* bv, float c[2][4][4])
{
#pragma unroll
    for (int ks = 0; ks < 2; ks++) {
        uint4 av[2];
#pragma unroll
        for (int i = 0; i < 2; i++)
            av[i] = *reinterpret_cast<const uint4*>(Ab + i * istr + ks * KS_STR);
#pragma unroll
        for (int i = 0; i < 2; i++)
            mma8(c[i], av[i], &bv[ks * 2]);
    }
}

__device__ __forceinline__ void zero_c(float c[2][4][4]) {
#pragma unroll
    for (int i = 0; i < 2; i++)
#pragma unroll
        for (int j = 0; j < 4; j++)
#pragma unroll
            for (int v = 0; v < 4; v++) c[i][j][v] = 0.0f;
}

__device__ __forceinline__ void store_T_frag(uint32_t* __restrict__ Tt, const float c[2][4][4],
                                             const float* bn, int iTb, int g, int t,
                                             int warpN, bool doSsp)
{
    const int ksBase = warpN >> 4;
#pragma unroll
    for (int i = 0; i < 2; i++)
#pragma unroll
        for (int half = 0; half < 2; half++)
#pragma unroll
            for (int j = 0; j < 4; j++) {
                float v0 = c[i][j][half * 2 + 0] + bn[j * 2 + 0];
                float v1 = c[i][j][half * 2 + 1] + bn[j * 2 + 1];
                if (doSsp) { v0 = sspf(v0); v1 = sspf(v1); }
                int ks = ksBase + (j >> 1);
                int w = half + 2 * (j & 1);
                Tt[(iTb + i) * TI_STR + ks * KS_STR + (g * 4 + t) * 4 + w] = h2(v0, v1);
            }
}

// ---------------- eattr pre-pack (tile-staged, coalesced) ----------
__global__ void __launch_bounds__(256) pack_eattr(const float* __restrict__ ea,
                                                  uint32_t* __restrict__ out) {
    __shared__ uint32_t sf[8192];
    const int tile = blockIdx.x;
    const int tid = threadIdx.x;
    const int row = tid >> 1;
    const int kh = tid & 1;
    const float* er = ea + ((size_t)tile * 128 + row) * EC;
    const int iT = row >> 4, rl = row & 15;
    const int g = rl & 7, hr = rl >> 3;
#pragma unroll
    for (int q = 0; q < 4; q++) {
#pragma unroll
        for (int f4 = 0; f4 < 4; f4++) {
            int kq = kh * 64 + (q * 4 + f4) * 4;
            float4 v = make_float4(0.f, 0.f, 0.f, 0.f);
            if (kq < EC) {
                if (kq + 3 < EC)
                    v = *reinterpret_cast<const float4*>(er + kq);
                else {
                    v.x = er[kq];
                    if (kq + 1 < EC) v.y = er[kq + 1];
                    if (kq + 2 < EC) v.z = er[kq + 2];
                }
            }
            int ks = kq >> 4, kl = kq & 15;
            int w = hr + ((kl & 8) ? 2 : 0);
            int t0 = (kl & 7) >> 1;
            uint32_t* p = sf + iT * 1024 + ks * 128 + (g * 4 + t0) * 4 + w;
            p[0] = h2(v.x, v.y);
            p[4] = h2(v.z, v.w);
        }
    }
    __syncthreads();
    uint32_t* o = out + (size_t)tile * 8192;
#pragma unroll
    for (int i = 0; i < 8; i++)
        *reinterpret_cast<uint4*>(o + (tid + i * 256) * 4) =
            *reinterpret_cast<const uint4*>(sf + (tid + i * 256) * 4);
}

// ---------------- fused edge kernel: 64-edge tiles, 2 CTAs/SM, kstep pipeline -----
__global__ void __launch_bounds__(NTE, 2) edge_fused(
    const uint32_t* __restrict__ eaf,
    const uint32_t* __restrict__ B1g, const float* __restrict__ b1,
    const uint32_t* __restrict__ B2g, const float* __restrict__ b2,
    const int2* __restrict__ meta,
    const uint32_t* __restrict__ xh, float* __restrict__ agg)
{
    extern __shared__ uint32_t sm[];
    uint32_t* Tt = sm;
    uint32_t* Wm = sm;

    const int tid = threadIdx.x;
    const int wid = tid >> 5, lane = tid & 31;
    const int g = lane >> 2, t = lane & 3;
    const int widm = wid & 1, widn = wid >> 1;
    const int warpM = widm * 32, warpN = widn * 32;
    const int mBase = blockIdx.x * 64;
    const int iTb = widm * 2;

    float c[2][4][4];
    zero_c(c);

    // stage 1: K trimmed to 112 (ksteps 0..6; kstep 7 is exact zeros both sides)
    const uint32_t* AfB = eaf + (size_t)(blockIdx.x >> 1) * 8192
                        + ((blockIdx.x & 1) * 4 + widm * 2) * 1024 + lane * 4;
    const uint32_t* B1b = B1g + (widn * 2) * 256 + lane * 4;
    uint4 a[2], b[2], an[2], bn_[2];
    ldA_e(a, AfB, 0);
    ldB_k(b, B1b, 0);
#pragma unroll
    for (int ks = 0; ks < 7; ks++) {
        if (ks < 6) { ldA_e(an, AfB, ks + 1); ldB_k(bn_, B1b, ks + 1); }
        mma8(c[0], a[0], b);
        mma8(c[1], a[1], b);
        if (ks < 6) { a[0] = an[0]; a[1] = an[1]; b[0] = bn_[0]; b[1] = bn_[1]; }
    }

    float bn1[8];
#pragma unroll
    for (int j = 0; j < 4; j++) {
        bn1[j * 2 + 0] = __ldg(b1 + warpN + j * 8 + t * 2 + 0);
        bn1[j * 2 + 1] = __ldg(b1 + warpN + j * 8 + t * 2 + 1);
    }
    store_T_frag(Tt, c, bn1, iTb, g, t, warpN, true);
    zero_c(c);
    __syncthreads();   // T visible to all warps

    // stage 2: T (smem) @ B2, kstep pipeline (K=128, 8 ksteps)
    const uint32_t* Ab = Tt + iTb * TI_STR + lane * 4;
    const uint32_t* B2b = B2g + (widn * 2) * 256 + lane * 4;
    ldA_s(a, Ab, 0);
    ldB_k(b, B2b, 0);
#pragma unroll
    for (int ks = 0; ks < 8; ks++) {
        if (ks < 7) { ldA_s(an, Ab, ks + 1); ldB_k(bn_, B2b, ks + 1); }
        mma8(c[0], a[0], b);
        mma8(c[1], a[1], b);
        if (ks < 7) { a[0] = an[0]; a[1] = an[1]; b[0] = bn_[0]; b[1] = bn_[1]; }
    }
    __syncthreads();   // done reading Tt; safe to overwrite with W

    // epilogue: W(+bias) -> smem half2
    float bn2[8];
#pragma unroll
    for (int j = 0; j < 4; j++) {
        bn2[j * 2 + 0] = __ldg(b2 + warpN + j * 8 + t * 2 + 0);
        bn2[j * 2 + 1] = __ldg(b2 + warpN + j * 8 + t * 2 + 1);
    }
#pragma unroll
    for (int i = 0; i < 2; i++)
#pragma unroll
        for (int half = 0; half < 2; half++) {
            const int row = warpM + i * 16 + g + half * 8;
#pragma unroll
            for (int j = 0; j < 4; j++) {
                float v0 = c[i][j][half * 2 + 0] + bn2[j * 2 + 0];
                float v1 = c[i][j][half * 2 + 1] + bn2[j * 2 + 1];
                Wm[row * WS_STR + (warpN >> 1) + j * 4 + t] = h2(v0, v1);
            }
        }
    __syncthreads();

    // warp-per-edge scatter: packed metadata, coalesced gather + red.v4
#pragma unroll
    for (int it = 0; it < 8; it++) {
        const int e = mBase + wid * 8 + it;
        const int2 mt = __ldg(meta + e);
        if (mt.x >= 0) {
            uint2 Wp = *reinterpret_cast<const uint2*>(Wm + (wid * 8 + it) * WS_STR + lane * 2);
            uint2 xp = __ldg(reinterpret_cast<const uint2*>(xh + (size_t)mt.x * 64 + lane * 2));
            float2 w01 = __half22float2(*reinterpret_cast<const __half2*>(&Wp.x));
            float2 w23 = __half22float2(*reinterpret_cast<const __half2*>(&Wp.y));
            float2 x01 = __half22float2(*reinterpret_cast<const __half2*>(&xp.x));
            float2 x23 = __half22float2(*reinterpret_cast<const __half2*>(&xp.y));
            float m0 = x01.x * w01.x, m1 = x01.y * w01.y;
            float m2 = x23.x * w23.x, m3 = x23.y * w23.y;
            asm volatile("red.global.add.v4.f32 [%0], {%1, %2, %3, %4};"
                         :: "l"(agg + (size_t)mt.y * 128 + lane * 4),
                            "f"(m0), "f"(m1), "f"(m2), "f"(m3) : "memory");
        }
    }
}

// ---------------- fused node kernel: 64-row tiles, 256 threads, 2 CTAs/SM ---------
__global__ void __launch_bounds__(NTE, 2) node_fused(
    const float* __restrict__ agg, float* __restrict__ aggW,
    const uint32_t* __restrict__ B1g, const float* __restrict__ b1,
    const uint32_t* __restrict__ B2g, const float* __restrict__ b2,
    float* __restrict__ h, const uint32_t* __restrict__ B3g, uint32_t* __restrict__ xOut)
{
    extern __shared__ uint32_t sm[];
    uint32_t* Tt  = sm;
    uint32_t* As0 = sm + TWORDS_N;
    uint32_t* As1 = As0 + AWORDS_N;

    const int tid = threadIdx.x;
    const int wid = tid >> 5, lane = tid & 31;
    const int g = lane >> 2, t = lane & 3;
    const int widm = wid & 1, widn = wid >> 1;
    const int warpM = widm * 32, warpN = widn * 32;
    const int mBase = blockIdx.x * 64;
    const int iTb = widm * 2;

    float c[2][4][4];
    zero_c(c);
    float4 aR[2];
    uint4 bv[4], bN[4];

    // stage 1: agg (smem-staged, double-buffered) @ B1; zero agg behind the read
    loadA_g(aR, agg, mBase, 0, N_NODES, 128, tid);
    zeroA_g(aggW, mBase, 0, N_NODES, 128, tid);
    loadB_frag(bv, B1g, 0, widn, lane);
    storeA_f(As0, aR, tid);
    __syncthreads();
#pragma unroll
    for (int ch = 0; ch < 4; ch++) {
        if (ch < 3) {
            loadA_g(aR, agg, mBase, (ch + 1) * 32, N_NODES, 128, tid);
            zeroA_g(aggW, mBase, (ch + 1) * 32, N_NODES, 128, tid);
            loadB_frag(bN, B1g, ch + 1, widn, lane);
        }
        mma_s_bv(((ch & 1) ? As1 : As0) + iTb * AI_STR + lane * 4, AI_STR, bv, c);
        if (ch < 3) {
            storeA_f(((ch + 1) & 1) ? As1 : As0, aR, tid);
#pragma unroll
            for (int q = 0; q < 4; q++) bv[q] = bN[q];
        }
        __syncthreads();
    }

    float bn1[8];
#pragma unroll
    for (int j = 0; j < 4; j++) {
        bn1[j * 2 + 0] = __ldg(b1 + warpN + j * 8 + t * 2 + 0);
        bn1[j * 2 + 1] = __ldg(b1 + warpN + j * 8 + t * 2 + 1);
    }
    store_T_frag(Tt, c, bn1, iTb, g, t, warpN, true);
    zero_c(c);
    loadB_frag(bv, B2g, 0, widn, lane);
    __syncthreads();

    // stage 2: T @ B2
    const uint32_t* Ab = Tt + iTb * TI_STR + lane * 4;
#pragma unroll
    for (int ch = 0; ch < 4; ch++) {
        if (ch < 3) loadB_frag(bN, B2g, ch + 1, widn, lane);
        mma_s_bv(Ab + ch * 2 * KS_STR, TI_STR, bv, c);
        if (ch < 3) {
#pragma unroll
            for (int q = 0; q < 4; q++) bv[q] = bN[q];
        }
    }
    __syncthreads();

    // stage-2 epilogue: h += residual; keep hnew resident in T-frag
    float bn2[8];
#pragma unroll
    for (int j = 0; j < 4; j++) {
        bn2[j * 2 + 0] = __ldg(b2 + warpN + j * 8 + t * 2 + 0);
        bn2[j * 2 + 1] = __ldg(b2 + warpN + j * 8 + t * 2 + 1);
    }
    const int ksBase = warpN >> 4;
#pragma unroll
    for (int i = 0; i < 2; i++)
#pragma unroll
        for (int half = 0; half < 2; half++) {
            const int gm = mBase + warpM + i * 16 + g + half * 8;
            const bool ok = gm < N_NODES;
            float* hrow = h + (size_t)gm * 128;
#pragma unroll
            for (int j = 0; j < 4; j++) {
                const int col = warpN + j * 8 + t * 2;
                float v0 = c[i][j][half * 2 + 0] + bn2[j * 2 + 0];
                float v1 = c[i][j][half * 2 + 1] + bn2[j * 2 + 1];
                if (ok) {
                    float2 hv = *reinterpret_cast<const float2*>(hrow + col);
                    v0 += hv.x; v1 += hv.y;
                    *reinterpret_cast<float2*>(hrow + col) = make_float2(v0, v1);
                }
                int ks = ksBase + (j >> 1);
                int w = half + 2 * (j & 1);
                Tt[(iTb + i) * TI_STR + ks * KS_STR + (g * 4 + t) * 4 + w] = h2(v0, v1);
            }
        }

    // stage 3: xOut(half2) = hnew @ lin1next
    if (B3g != nullptr) {
        zero_c(c);
        loadB_frag(bv, B3g, 0, widn, lane);
        __syncthreads();
#pragma unroll
        for (int ch = 0; ch < 4; ch++) {
            if (ch < 3) loadB_frag(bN, B3g, ch + 1, widn, lane);
            mma_s_bv(Ab + ch * 2 * KS_STR, TI_STR, bv, c);
            if (ch < 3) {
#pragma unroll
                for (int q = 0; q < 4; q++) bv[q] = bN[q];
            }
        }
#pragma unroll
        for (int i = 0; i < 2; i++)
#pragma unroll
            for (int half = 0; half < 2; half++) {
                const int gm = mBase + warpM + i * 16 + g + half * 8;
                if (gm < N_NODES) {
                    uint32_t* orow = xOut + (size_t)gm * 64;
#pragma unroll
                    for (int j = 0; j < 4; j++) {
                        const int col = warpN + j * 8 + t * 2;
                        orow[col >> 1] = h2(c[i][j][half * 2 + 0], c[i][j][half * 2 + 1]);
                    }
                }
            }
    }
}

// ---------------- plain GEMM: 64-row tiles, 256 threads, 2 CTAs/SM ----------------
__global__ void __launch_bounds__(NTE, 2) gemm_plain(
    const float* __restrict__ A, const uint32_t* __restrict__ Bg,
    uint32_t* __restrict__ out, int M)
{
    extern __shared__ uint32_t sm[];
    uint32_t* As0 = sm;
    uint32_t* As1 = As0 + AWORDS_N;

    const int tid = threadIdx.x;
    const int wid = tid >> 5, lane = tid & 31;
    const int g = lane >> 2, t = lane & 3;
    const int widm = wid & 1, widn = wid >> 1;
    const int warpM = widm * 32, warpN = widn * 32;
    const int mBase = blockIdx.x * 64;
    const int iTb = widm * 2;

    float c[2][4][4];
    zero_c(c);
    float4 aR[2];
    uint4 bv[4], bN[4];
    loadA_g(aR, A, mBase, 0, M, 128, tid);
    loadB_frag(bv, Bg, 0, widn, lane);
    storeA_f(As0, aR, tid);
    __syncthreads();
#pragma unroll
    for (int ch = 0; ch < 4; ch++) {
        if (ch < 3) {
            loadA_g(aR, A, mBase, (ch + 1) * 32, M, 128, tid);
            loadB_frag(bN, Bg, ch + 1, widn, lane);
        }
        mma_s_bv(((ch & 1) ? As1 : As0) + iTb * AI_STR + lane * 4, AI_STR, bv, c);
        if (ch < 3) {
            storeA_f(((ch + 1) & 1) ? As1 : As0, aR, tid);
#pragma unroll
            for (int q = 0; q < 4; q++) bv[q] = bN[q];
        }
        __syncthreads();
    }
#pragma unroll
    for (int i = 0; i < 2; i++)
#pragma unroll
        for (int half = 0; half < 2; half++) {
            const int gm = mBase + warpM + i * 16 + g + half * 8;
            if (gm < M) {
                uint32_t* orow = out + (size_t)gm * 64;
#pragma unroll
                for (int j = 0; j < 4; j++) {
                    const int col = warpN + j * 8 + t * 2;
                    orow[col >> 1] = h2(c[i][j][half * 2 + 0], c[i][j][half * 2 + 1]);
                }
            }
        }
}

// ---------------- small kernels ----------------
__global__ void embed_kernel(const float* __restrict__ z, const float* __restrict__ w,
                             const float* __restrict__ b, float* __restrict__ h) {
    int n = blockIdx.x, j = threadIdx.x;
    const float* zr = z + (size_t)n * (IN_DIM + HID);
    float acc = b[j] + zr[IN_DIM + j];
#pragma unroll
    for (int k = 0; k < IN_DIM; k++) acc = fmaf(zr[k], w[k * HID + j], acc);
    h[(size_t)n * HID + j] = acc;
}

__global__ void pack_meta(const float* __restrict__ len, const int* __restrict__ src,
                          const int* __restrict__ dst, int2* __restrict__ meta) {
    int e = blockIdx.x * 256 + threadIdx.x;
    if (e < N_EDGES) {
        float l = len[e];
        bool ok = (l <= 10.0f && l >= 0.0f);
        meta[e] = make_int2(ok ? src[e] : -1, dst[e]);
    }
}

// ---------------- host launch ----------------
extern "C" void kernel_launch(void* const* d_in, const int* in_sizes, int n_in,
                              void* d_out, int out_size) {
    const float* z      = (const float*)d_in[0];
    const int*   ei     = (const int*)  d_in[1];
    const float* elen   = (const float*)d_in[2];
    const float* eattr  = (const float*)d_in[3];
    const float* emb_w  = (const float*)d_in[4];
    const float* emb_b  = (const float*)d_in[5];
    const float* lin1_w = (const float*)d_in[6];
    const float* nn_w1  = (const float*)d_in[7];
    const float* nn_b1  = (const float*)d_in[8];
    const float* nn_w2  = (const float*)d_in[9];
    const float* nn_b2  = (const float*)d_in[10];
    const float* lin2_w = (const float*)d_in[11];
    const float* lin2_b = (const float*)d_in[12];
    const float* lin_w  = (const float*)d_in[13];
    const float* lin_b  = (const float*)d_in[14];
    float* h = (float*)d_out;

    float* pagg;
    int2* pmeta;
    uint32_t *pxh, *peaf, *pw1, *pw2, *pl2, *pl, *pl1;
    cudaGetSymbolAddress((void**)&pxh,   g_xh);
    cudaGetSymbolAddress((void**)&pagg,  g_agg);
    cudaGetSymbolAddress((void**)&pmeta, g_meta);
    cudaGetSymbolAddress((void**)&peaf,  g_eaf);
    cudaGetSymbolAddress((void**)&pw1,   g_w1f);
    cudaGetSymbolAddress((void**)&pw2,   g_w2f);
    cudaGetSymbolAddress((void**)&pl2,   g_l2f);
    cudaGetSymbolAddress((void**)&pl,    g_lf);
    cudaGetSymbolAddress((void**)&pl1,   g_l1f);

    cudaFuncSetAttribute(edge_fused, cudaFuncAttributeMaxDynamicSharedMemorySize, EDGE_SMEM);
    cudaFuncSetAttribute(node_fused, cudaFuncAttributeMaxDynamicSharedMemorySize, NODE_SMEM);
    cudaFuncSetAttribute(gemm_plain, cudaFuncAttributeMaxDynamicSharedMemorySize, PLAIN_SMEM);

    const int* src = ei;
    const int* dst = ei + N_EDGES;

    embed_kernel<<<N_NODES, HID>>>(z, emb_w, emb_b, h);
    pack_meta<<<(N_EDGES + 255) / 256, 256>>>(elen, src, dst, pmeta);
    pack_eattr<<<NTILES, 256>>>(eattr, peaf);
    {
        dim3 gw((6 * 8192 + 255) / 256, 5);
        pack_w<<<gw, 256>>>(nn_w1, nn_w2, lin2_w, lin_w, lin1_w, pw1, pw2, pl2, pl, pl1);
    }

    gemm_plain<<<NODETILES, NTE, PLAIN_SMEM>>>(h, pl1, pxh, N_NODES);

    for (int i = 0; i < N_BLOCKS; i++) {
        edge_fused<<<ETILES, NTE, EDGE_SMEM>>>(
            peaf, pw1 + i * 8192, nn_b1 + (size_t)i * HID,
            pw2 + i * 8192, nn_b2 + (size_t)i * HID,
            pmeta, pxh, pagg);
        const uint32_t* lin1next = (i + 1 < N_BLOCKS) ? (pl1 + (i + 1) * 8192) : nullptr;
        node_fused<<<NODETILES, NTE, NODE_SMEM>>>(
            pagg, pagg, pl2 + i * 8192, lin2_b + (size_t)i * HID,
            pl + i * 8192, lin_b + (size_t)i * HID,
            h, lin1next, pxh);
    }
}